// round 7
// baseline (speedup 1.0000x reference)
#include <cuda_runtime.h>
#include <cstdint>

// Problem dims
#define H_   8
#define IN_  512
#define SEQ_ 1024
#define MID_ 2048

constexpr int BM = 128, BN = 128, BK = 16;

// ---------------- scratch (device globals; no allocation allowed) ----------------
__device__ float g_qkv [3 * IN_ * SEQ_];          //  6 MB
__device__ float g_hbuf[H_ * 3 * IN_ * MID_];     // 96 MB
__device__ float g_sq  [H_ * 3 * IN_ * SEQ_];     // 48 MB
__device__ float g_bmat[H_ * SEQ_ * SEQ_];        // 32 MB
__device__ float g_att [H_ * IN_ * SEQ_];         // 16 MB
__device__ float g_z1  [MID_ * SEQ_];             //  8 MB
__device__ float g_mout[IN_ * SEQ_];
__device__ float g_x1  [IN_ * SEQ_];
__device__ float g_x2  [IN_ * SEQ_];
__device__ float g_t   [MID_ * SEQ_];             //  8 MB

// ---------------- tf32 helpers ----------------
__device__ __forceinline__ uint32_t f2tf32(float x) {
    uint32_t y;
    asm("cvt.rna.tf32.f32 %0, %1;" : "=r"(y) : "f"(x));
    return y;
}

__device__ __forceinline__ void mma_tf32(float c[4], const uint32_t a[4], const uint32_t b[2]) {
    asm volatile(
        "mma.sync.aligned.m16n8k8.row.col.f32.tf32.tf32.f32 "
        "{%0,%1,%2,%3}, {%4,%5,%6,%7}, {%8,%9}, {%0,%1,%2,%3};\n"
        : "+f"(c[0]), "+f"(c[1]), "+f"(c[2]), "+f"(c[3])
        : "r"(a[0]), "r"(a[1]), "r"(a[2]), "r"(a[3]), "r"(b[0]), "r"(b[1]));
}

// ---------------- generic batched GEMM: C = act( op(A) * op(B) [+ Res] ) ----------------
// A: !TA -> (M,K) row-major ; TA -> stored (K,M)
// B: !TB -> (K,N) row-major ; TB -> stored (N,K)
// C: (M,N) row-major. RA/RB: relu applied to A/B elements on load.
// RO: relu on output. RES: C += Res (Res same layout as C, no batch stride needed here).
// 3xTF32 split precision: fp32-quality results from tf32 tensor cores.
template<bool TA, bool TB, bool RA, bool RB, bool RO, bool RES>
__global__ void __launch_bounds__(256)
gemm_tf32(const float* __restrict__ A, const float* __restrict__ B,
          float* __restrict__ C, const float* __restrict__ Res,
          int M, int N, int K, long long sA, long long sB, long long sC)
{
    A += (long long)blockIdx.z * sA;
    B += (long long)blockIdx.z * sB;
    C += (long long)blockIdx.z * sC;

    const int bm = blockIdx.y * BM;
    const int bn = blockIdx.x * BN;

    __shared__ uint32_t AsHi[BK][BM + 1];
    __shared__ uint32_t AsLo[BK][BM + 1];
    __shared__ uint32_t BsHi[BK][BN + 1];
    __shared__ uint32_t BsLo[BK][BN + 1];

    const int tid  = threadIdx.x;
    const int lane = tid & 31;
    const int warp = tid >> 5;
    const int wm = (warp & 1) * 64;   // 2 warps along M
    const int wn = (warp >> 1) * 32;  // 4 warps along N
    const int ar = lane >> 2;         // mma group id
    const int ac = lane & 3;          // mma thread-in-group

    float acc[4][4][4];
#pragma unroll
    for (int i = 0; i < 4; ++i)
#pragma unroll
        for (int j = 0; j < 4; ++j)
#pragma unroll
            for (int r = 0; r < 4; ++r) acc[i][j][r] = 0.f;

    for (int k0 = 0; k0 < K; k0 += BK) {
        // ---- stage A tile (128 x 16) ----
#pragma unroll
        for (int it = 0; it < (BM * BK) / 256; ++it) {
            int idx = tid + it * 256;
            int mm, kk;
            long long gidx;
            if (!TA) { mm = idx >> 4;  kk = idx & 15;  gidx = (long long)(bm + mm) * K + (k0 + kk); }
            else     { kk = idx >> 7;  mm = idx & 127; gidx = (long long)(k0 + kk) * M + (bm + mm); }
            float v = A[gidx];
            if (RA) v = fmaxf(v, 0.f);
            uint32_t hi = f2tf32(v);
            AsHi[kk][mm] = hi;
            AsLo[kk][mm] = f2tf32(v - __uint_as_float(hi));
        }
        // ---- stage B tile (16 x 128) ----
#pragma unroll
        for (int it = 0; it < (BN * BK) / 256; ++it) {
            int idx = tid + it * 256;
            int nn, kk;
            long long gidx;
            if (!TB) { kk = idx >> 7;  nn = idx & 127; gidx = (long long)(k0 + kk) * N + (bn + nn); }
            else     { nn = idx >> 4;  kk = idx & 15;  gidx = (long long)(bn + nn) * K + (k0 + kk); }
            float v = B[gidx];
            if (RB) v = fmaxf(v, 0.f);
            uint32_t hi = f2tf32(v);
            BsHi[kk][nn] = hi;
            BsLo[kk][nn] = f2tf32(v - __uint_as_float(hi));
        }
        __syncthreads();

#pragma unroll
        for (int kk = 0; kk < BK; kk += 8) {
            uint32_t a[4][4], a2[4][4], b[4][2];
            // hi(A)
#pragma unroll
            for (int i = 0; i < 4; ++i) {
                int m0 = wm + i * 16 + ar;
                a[i][0] = AsHi[kk + ac][m0];
                a[i][1] = AsHi[kk + ac][m0 + 8];
                a[i][2] = AsHi[kk + ac + 4][m0];
                a[i][3] = AsHi[kk + ac + 4][m0 + 8];
            }
            // hi(B)
#pragma unroll
            for (int j = 0; j < 4; ++j) {
                int n0 = wn + j * 8 + ar;
                b[j][0] = BsHi[kk + ac][n0];
                b[j][1] = BsHi[kk + ac + 4][n0];
            }
            // hi*hi
#pragma unroll
            for (int i = 0; i < 4; ++i)
#pragma unroll
                for (int j = 0; j < 4; ++j) mma_tf32(acc[i][j], a[i], b[j]);
            // lo(A) * hi(B)
#pragma unroll
            for (int i = 0; i < 4; ++i) {
                int m0 = wm + i * 16 + ar;
                a2[i][0] = AsLo[kk + ac][m0];
                a2[i][1] = AsLo[kk + ac][m0 + 8];
                a2[i][2] = AsLo[kk + ac + 4][m0];
                a2[i][3] = AsLo[kk + ac + 4][m0 + 8];
            }
#pragma unroll
            for (int i = 0; i < 4; ++i)
#pragma unroll
                for (int j = 0; j < 4; ++j) mma_tf32(acc[i][j], a2[i], b[j]);
            // hi(A) * lo(B)
#pragma unroll
            for (int j = 0; j < 4; ++j) {
                int n0 = wn + j * 8 + ar;
                b[j][0] = BsLo[kk + ac][n0];
                b[j][1] = BsLo[kk + ac + 4][n0];
            }
#pragma unroll
            for (int i = 0; i < 4; ++i)
#pragma unroll
                for (int j = 0; j < 4; ++j) mma_tf32(acc[i][j], a[i], b[j]);
        }
        __syncthreads();
    }

    // ---- epilogue ----
#pragma unroll
    for (int i = 0; i < 4; ++i) {
        int m0 = bm + wm + i * 16 + ar;
#pragma unroll
        for (int j = 0; j < 4; ++j) {
            int n0 = bn + wn + j * 8 + ac * 2;
            long long o0 = (long long)m0 * N + n0;
            long long o1 = o0 + 8LL * N;
            float v0 = acc[i][j][0], v1 = acc[i][j][1];
            float v2 = acc[i][j][2], v3 = acc[i][j][3];
            if (RES) {
                v0 += Res[o0]; v1 += Res[o0 + 1];
                v2 += Res[o1]; v3 += Res[o1 + 1];
            }
            if (RO) {
                v0 = fmaxf(v0, 0.f); v1 = fmaxf(v1, 0.f);
                v2 = fmaxf(v2, 0.f); v3 = fmaxf(v3, 0.f);
            }
            C[o0] = v0; C[o0 + 1] = v1;
            C[o1] = v2; C[o1 + 1] = v3;
        }
    }
}

// ---------------- fused residual add + layernorm over last axis (1024) ----------------
__global__ void add_ln_kernel(const float* __restrict__ a, const float* __restrict__ b,
                              const float* __restrict__ w, const float* __restrict__ bias,
                              float* __restrict__ out)
{
    const int row = blockIdx.x;
    const int tid = threadIdx.x;
    const long long base = (long long)row * SEQ_;
    float v[4];
    float s = 0.f, ss = 0.f;
#pragma unroll
    for (int i = 0; i < 4; ++i) {
        int col = tid + i * 256;
        float t = a[base + col] + b[base + col];
        v[i] = t; s += t; ss += t * t;
    }
#pragma unroll
    for (int o = 16; o > 0; o >>= 1) {
        s  += __shfl_xor_sync(0xffffffffu, s,  o);
        ss += __shfl_xor_sync(0xffffffffu, ss, o);
    }
    __shared__ float rs[8], rss[8];
    if ((tid & 31) == 0) { rs[tid >> 5] = s; rss[tid >> 5] = ss; }
    __syncthreads();
    s = 0.f; ss = 0.f;
#pragma unroll
    for (int i = 0; i < 8; ++i) { s += rs[i]; ss += rss[i]; }
    const float mu  = s  * (1.0f / SEQ_);
    const float var = ss * (1.0f / SEQ_) - mu * mu;
    const float inv = rsqrtf(var + 1e-6f);
#pragma unroll
    for (int i = 0; i < 4; ++i) {
        int col = tid + i * 256;
        out[base + col] = (v[i] - mu) * inv * w[col] + bias[col];
    }
}

// ---------------- host orchestration ----------------
static void launch_mha(const float* x, const float* wqkv, const float* W1, const float* W2,
                       const float* cW1, const float* cW2,
                       float* qkv, float* hbuf, float* sq, float* bmat, float* att,
                       float* z1, float* mout)
{
    // 1. qkv[c] = w_qkv[c] @ x                     (512,1024,K=512) x3
    gemm_tf32<false,false,false,false,false,false><<<dim3(SEQ_/BN, IN_/BM, 3), 256>>>(
        wqkv, x, qkv, nullptr, IN_, SEQ_, IN_,
        (long long)IN_*IN_, 0, (long long)IN_*SEQ_);
    // 2. h[h,c] = relu( relu(qkv[c]) @ W1[h,c]^T ) (512,2048,K=1024) x24
    for (int c = 0; c < 3; ++c)
        gemm_tf32<false,true,true,false,true,false><<<dim3(MID_/BN, IN_/BM, H_), 256>>>(
            qkv + (long long)c*IN_*SEQ_, W1 + (long long)c*MID_*SEQ_,
            hbuf + (long long)c*IN_*MID_, nullptr,
            IN_, MID_, SEQ_,
            0, (long long)3*MID_*SEQ_, (long long)3*IN_*MID_);
    // 3. sq[h,c] = h[h,c] @ W2[h,c]^T              (512,1024,K=2048) x24
    for (int c = 0; c < 3; ++c)
        gemm_tf32<false,true,false,false,false,false><<<dim3(SEQ_/BN, IN_/BM, H_), 256>>>(
            hbuf + (long long)c*IN_*MID_, W2 + (long long)c*SEQ_*MID_,
            sq + (long long)c*IN_*SEQ_, nullptr,
            IN_, SEQ_, MID_,
            (long long)3*IN_*MID_, (long long)3*SEQ_*MID_, (long long)3*IN_*SEQ_);
    // 4. b[h] = k[h]^T @ q[h]                      (1024,1024,K=512) x8  (TN)
    gemm_tf32<true,false,false,false,false,false><<<dim3(SEQ_/BN, SEQ_/BM, H_), 256>>>(
        sq + (long long)IN_*SEQ_, sq, bmat, nullptr,
        SEQ_, SEQ_, IN_,
        (long long)3*IN_*SEQ_, (long long)3*IN_*SEQ_, (long long)SEQ_*SEQ_);
    // 5. att[h] = v[h] @ b[h]                      (512,1024,K=1024) x8
    gemm_tf32<false,false,false,false,false,false><<<dim3(SEQ_/BN, IN_/BM, H_), 256>>>(
        sq + (long long)2*IN_*SEQ_, bmat, att, nullptr,
        IN_, SEQ_, SEQ_,
        (long long)3*IN_*SEQ_, (long long)SEQ_*SEQ_, (long long)IN_*SEQ_);
    // 6. z1t = relu( cW1 @ relu(att_flat) )        (2048,1024,K=4096)
    gemm_tf32<false,false,false,true,true,false><<<dim3(SEQ_/BN, MID_/BM, 1), 256>>>(
        cW1, att, z1, nullptr, MID_, SEQ_, H_*IN_, 0, 0, 0);
    // 7. mout = cW2 @ relu(z1t)                    (512,1024,K=2048)
    gemm_tf32<false,false,false,true,false,false><<<dim3(SEQ_/BN, IN_/BM, 1), 256>>>(
        cW2, z1, mout, nullptr, IN_, SEQ_, MID_, 0, 0, 0);
}

static void launch_ffn(const float* x2, const float* Wa, const float* Wb,
                       float* t, float* out)
{
    // t = relu( Wa @ relu(x2) )                    (2048,1024,K=512)
    gemm_tf32<false,false,false,true,true,false><<<dim3(SEQ_/BN, MID_/BM, 1), 256>>>(
        Wa, x2, t, nullptr, MID_, SEQ_, IN_, 0, 0, 0);
    // out = Wb @ relu(t) + x2                      (512,1024,K=2048)
    gemm_tf32<false,false,false,true,false,true><<<dim3(SEQ_/BN, IN_/BM, 1), 256>>>(
        Wb, t, out, x2, IN_, SEQ_, MID_, 0, 0, 0);
}

extern "C" void kernel_launch(void* const* d_in, const int* in_sizes, int n_in,
                              void* d_out, int out_size)
{
    (void)in_sizes; (void)n_in; (void)out_size;

    const float* inp     = (const float*)d_in[0];
    const float* w_qkv_1 = (const float*)d_in[1];
    const float* w_qkv_2 = (const float*)d_in[2];
    const float* mh1_W1  = (const float*)d_in[3];
    const float* mh1_W2  = (const float*)d_in[4];
    const float* mh2_W1  = (const float*)d_in[5];
    const float* mh2_W2  = (const float*)d_in[6];
    const float* c1_W1   = (const float*)d_in[7];
    const float* c1_W2   = (const float*)d_in[8];
    const float* c2_W1   = (const float*)d_in[9];
    const float* c2_W2   = (const float*)d_in[10];
    const float* l1_W1   = (const float*)d_in[11];
    const float* l1_W2   = (const float*)d_in[12];
    const float* l2_W1   = (const float*)d_in[13];
    const float* l2_W2   = (const float*)d_in[14];
    const float* norm_w  = (const float*)d_in[15];
    const float* norm_b  = (const float*)d_in[16];
    float* out = (float*)d_out;

    float *qkv, *hbuf, *sq, *bmat, *att, *z1, *mout, *x1, *x2, *t;
    cudaGetSymbolAddress((void**)&qkv,  g_qkv);
    cudaGetSymbolAddress((void**)&hbuf, g_hbuf);
    cudaGetSymbolAddress((void**)&sq,   g_sq);
    cudaGetSymbolAddress((void**)&bmat, g_bmat);
    cudaGetSymbolAddress((void**)&att,  g_att);
    cudaGetSymbolAddress((void**)&z1,   g_z1);
    cudaGetSymbolAddress((void**)&mout, g_mout);
    cudaGetSymbolAddress((void**)&x1,   g_x1);
    cudaGetSymbolAddress((void**)&x2,   g_x2);
    cudaGetSymbolAddress((void**)&t,    g_t);

    // Block 1: x1 = LN(inp + MHA1(inp))
    launch_mha(inp, w_qkv_1, mh1_W1, mh1_W2, c1_W1, c1_W2,
               qkv, hbuf, sq, bmat, att, z1, mout);
    add_ln_kernel<<<IN_, 256>>>(inp, mout, norm_w, norm_b, x1);

    // Block 2: x2 = LN(inp + MHA2(x1))   (note: residual is inp, per reference)
    launch_mha(x1, w_qkv_2, mh2_W1, mh2_W2, c2_W1, c2_W2,
               qkv, hbuf, sq, bmat, att, z1, mout);
    add_ln_kernel<<<IN_, 256>>>(inp, mout, norm_w, norm_b, x2);

    // Two FFN heads
    launch_ffn(x2, l1_W1, l1_W2, t, out);
    launch_ffn(x2, l2_W1, l2_W2, t, out + (long long)IN_ * SEQ_);
}

// round 8
// speedup vs baseline: 1.0007x; 1.0007x over previous
#include <cuda_runtime.h>
#include <cstdint>

// Problem dims
#define H_   8
#define IN_  512
#define SEQ_ 1024
#define MID_ 2048

constexpr int BM = 128, BN = 128, BK = 16;

// ---------------- scratch (device globals; no allocation allowed) ----------------
__device__ float g_qkv [3 * IN_ * SEQ_];          //  6 MB
__device__ float g_hbuf[H_ * 3 * IN_ * MID_];     // 96 MB
__device__ float g_sq  [H_ * 3 * IN_ * SEQ_];     // 48 MB
__device__ float g_bmat[H_ * SEQ_ * SEQ_];        // 32 MB
__device__ float g_att [H_ * IN_ * SEQ_];         // 16 MB
__device__ float g_z1  [MID_ * SEQ_];             //  8 MB
__device__ float g_mout[IN_ * SEQ_];
__device__ float g_x1  [IN_ * SEQ_];
__device__ float g_x2  [IN_ * SEQ_];
__device__ float g_t   [MID_ * SEQ_];             //  8 MB

// ---------------- tf32 helpers ----------------
__device__ __forceinline__ uint32_t f2tf32(float x) {
    uint32_t y;
    asm("cvt.rna.tf32.f32 %0, %1;" : "=r"(y) : "f"(x));
    return y;
}

__device__ __forceinline__ void mma_tf32(float c[4], const uint32_t a[4], const uint32_t b[2]) {
    asm volatile(
        "mma.sync.aligned.m16n8k8.row.col.f32.tf32.tf32.f32 "
        "{%0,%1,%2,%3}, {%4,%5,%6,%7}, {%8,%9}, {%0,%1,%2,%3};\n"
        : "+f"(c[0]), "+f"(c[1]), "+f"(c[2]), "+f"(c[3])
        : "r"(a[0]), "r"(a[1]), "r"(a[2]), "r"(a[3]), "r"(b[0]), "r"(b[1]));
}

// ---------------- generic batched GEMM: C = act( op(A) * op(B) [+ Res] ) ----------------
// A: !TA -> (M,K) row-major ; TA -> stored (K,M)
// B: !TB -> (K,N) row-major ; TB -> stored (N,K)
// C: (M,N) row-major. RA/RB: relu applied to A/B elements on load.
// RO: relu on output. RES: C += Res (Res same layout as C, no batch stride needed here).
// 3xTF32 split precision: fp32-quality results from tf32 tensor cores.
template<bool TA, bool TB, bool RA, bool RB, bool RO, bool RES>
__global__ void __launch_bounds__(256)
gemm_tf32(const float* __restrict__ A, const float* __restrict__ B,
          float* __restrict__ C, const float* __restrict__ Res,
          int M, int N, int K, long long sA, long long sB, long long sC)
{
    A += (long long)blockIdx.z * sA;
    B += (long long)blockIdx.z * sB;
    C += (long long)blockIdx.z * sC;

    const int bm = blockIdx.y * BM;
    const int bn = blockIdx.x * BN;

    __shared__ uint32_t AsHi[BK][BM + 1];
    __shared__ uint32_t AsLo[BK][BM + 1];
    __shared__ uint32_t BsHi[BK][BN + 1];
    __shared__ uint32_t BsLo[BK][BN + 1];

    const int tid  = threadIdx.x;
    const int lane = tid & 31;
    const int warp = tid >> 5;
    const int wm = (warp & 1) * 64;   // 2 warps along M
    const int wn = (warp >> 1) * 32;  // 4 warps along N
    const int ar = lane >> 2;         // mma group id
    const int ac = lane & 3;          // mma thread-in-group

    float acc[4][4][4];
#pragma unroll
    for (int i = 0; i < 4; ++i)
#pragma unroll
        for (int j = 0; j < 4; ++j)
#pragma unroll
            for (int r = 0; r < 4; ++r) acc[i][j][r] = 0.f;

    for (int k0 = 0; k0 < K; k0 += BK) {
        // ---- stage A tile (128 x 16) ----
#pragma unroll
        for (int it = 0; it < (BM * BK) / 256; ++it) {
            int idx = tid + it * 256;
            int mm, kk;
            long long gidx;
            if (!TA) { mm = idx >> 4;  kk = idx & 15;  gidx = (long long)(bm + mm) * K + (k0 + kk); }
            else     { kk = idx >> 7;  mm = idx & 127; gidx = (long long)(k0 + kk) * M + (bm + mm); }
            float v = A[gidx];
            if (RA) v = fmaxf(v, 0.f);
            uint32_t hi = f2tf32(v);
            AsHi[kk][mm] = hi;
            AsLo[kk][mm] = f2tf32(v - __uint_as_float(hi));
        }
        // ---- stage B tile (16 x 128) ----
#pragma unroll
        for (int it = 0; it < (BN * BK) / 256; ++it) {
            int idx = tid + it * 256;
            int nn, kk;
            long long gidx;
            if (!TB) { kk = idx >> 7;  nn = idx & 127; gidx = (long long)(k0 + kk) * N + (bn + nn); }
            else     { nn = idx >> 4;  kk = idx & 15;  gidx = (long long)(bn + nn) * K + (k0 + kk); }
            float v = B[gidx];
            if (RB) v = fmaxf(v, 0.f);
            uint32_t hi = f2tf32(v);
            BsHi[kk][nn] = hi;
            BsLo[kk][nn] = f2tf32(v - __uint_as_float(hi));
        }
        __syncthreads();

#pragma unroll
        for (int kk = 0; kk < BK; kk += 8) {
            uint32_t a[4][4], a2[4][4], b[4][2];
            // hi(A)
#pragma unroll
            for (int i = 0; i < 4; ++i) {
                int m0 = wm + i * 16 + ar;
                a[i][0] = AsHi[kk + ac][m0];
                a[i][1] = AsHi[kk + ac][m0 + 8];
                a[i][2] = AsHi[kk + ac + 4][m0];
                a[i][3] = AsHi[kk + ac + 4][m0 + 8];
            }
            // hi(B)
#pragma unroll
            for (int j = 0; j < 4; ++j) {
                int n0 = wn + j * 8 + ar;
                b[j][0] = BsHi[kk + ac][n0];
                b[j][1] = BsHi[kk + ac + 4][n0];
            }
            // hi*hi
#pragma unroll
            for (int i = 0; i < 4; ++i)
#pragma unroll
                for (int j = 0; j < 4; ++j) mma_tf32(acc[i][j], a[i], b[j]);
            // lo(A) * hi(B)
#pragma unroll
            for (int i = 0; i < 4; ++i) {
                int m0 = wm + i * 16 + ar;
                a2[i][0] = AsLo[kk + ac][m0];
                a2[i][1] = AsLo[kk + ac][m0 + 8];
                a2[i][2] = AsLo[kk + ac + 4][m0];
                a2[i][3] = AsLo[kk + ac + 4][m0 + 8];
            }
#pragma unroll
            for (int i = 0; i < 4; ++i)
#pragma unroll
                for (int j = 0; j < 4; ++j) mma_tf32(acc[i][j], a2[i], b[j]);
            // hi(A) * lo(B)
#pragma unroll
            for (int j = 0; j < 4; ++j) {
                int n0 = wn + j * 8 + ar;
                b[j][0] = BsLo[kk + ac][n0];
                b[j][1] = BsLo[kk + ac + 4][n0];
            }
#pragma unroll
            for (int i = 0; i < 4; ++i)
#pragma unroll
                for (int j = 0; j < 4; ++j) mma_tf32(acc[i][j], a[i], b[j]);
        }
        __syncthreads();
    }

    // ---- epilogue ----
#pragma unroll
    for (int i = 0; i < 4; ++i) {
        int m0 = bm + wm + i * 16 + ar;
#pragma unroll
        for (int j = 0; j < 4; ++j) {
            int n0 = bn + wn + j * 8 + ac * 2;
            long long o0 = (long long)m0 * N + n0;
            long long o1 = o0 + 8LL * N;
            float v0 = acc[i][j][0], v1 = acc[i][j][1];
            float v2 = acc[i][j][2], v3 = acc[i][j][3];
            if (RES) {
                v0 += Res[o0]; v1 += Res[o0 + 1];
                v2 += Res[o1]; v3 += Res[o1 + 1];
            }
            if (RO) {
                v0 = fmaxf(v0, 0.f); v1 = fmaxf(v1, 0.f);
                v2 = fmaxf(v2, 0.f); v3 = fmaxf(v3, 0.f);
            }
            C[o0] = v0; C[o0 + 1] = v1;
            C[o1] = v2; C[o1 + 1] = v3;
        }
    }
}

// ---------------- fused residual add + layernorm over last axis (1024) ----------------
__global__ void add_ln_kernel(const float* __restrict__ a, const float* __restrict__ b,
                              const float* __restrict__ w, const float* __restrict__ bias,
                              float* __restrict__ out)
{
    const int row = blockIdx.x;
    const int tid = threadIdx.x;
    const long long base = (long long)row * SEQ_;
    float v[4];
    float s = 0.f, ss = 0.f;
#pragma unroll
    for (int i = 0; i < 4; ++i) {
        int col = tid + i * 256;
        float t = a[base + col] + b[base + col];
        v[i] = t; s += t; ss += t * t;
    }
#pragma unroll
    for (int o = 16; o > 0; o >>= 1) {
        s  += __shfl_xor_sync(0xffffffffu, s,  o);
        ss += __shfl_xor_sync(0xffffffffu, ss, o);
    }
    __shared__ float rs[8], rss[8];
    if ((tid & 31) == 0) { rs[tid >> 5] = s; rss[tid >> 5] = ss; }
    __syncthreads();
    s = 0.f; ss = 0.f;
#pragma unroll
    for (int i = 0; i < 8; ++i) { s += rs[i]; ss += rss[i]; }
    const float mu  = s  * (1.0f / SEQ_);
    const float var = ss * (1.0f / SEQ_) - mu * mu;
    const float inv = rsqrtf(var + 1e-6f);
#pragma unroll
    for (int i = 0; i < 4; ++i) {
        int col = tid + i * 256;
        out[base + col] = (v[i] - mu) * inv * w[col] + bias[col];
    }
}

// ---------------- host orchestration ----------------
static void launch_mha(const float* x, const float* wqkv, const float* W1, const float* W2,
                       const float* cW1, const float* cW2,
                       float* qkv, float* hbuf, float* sq, float* bmat, float* att,
                       float* z1, float* mout)
{
    // 1. qkv[c] = w_qkv[c] @ x                     (512,1024,K=512) x3
    gemm_tf32<false,false,false,false,false,false><<<dim3(SEQ_/BN, IN_/BM, 3), 256>>>(
        wqkv, x, qkv, nullptr, IN_, SEQ_, IN_,
        (long long)IN_*IN_, 0, (long long)IN_*SEQ_);
    // 2. h[h,c] = relu( relu(qkv[c]) @ W1[h,c]^T ) (512,2048,K=1024) x24
    for (int c = 0; c < 3; ++c)
        gemm_tf32<false,true,true,false,true,false><<<dim3(MID_/BN, IN_/BM, H_), 256>>>(
            qkv + (long long)c*IN_*SEQ_, W1 + (long long)c*MID_*SEQ_,
            hbuf + (long long)c*IN_*MID_, nullptr,
            IN_, MID_, SEQ_,
            0, (long long)3*MID_*SEQ_, (long long)3*IN_*MID_);
    // 3. sq[h,c] = h[h,c] @ W2[h,c]^T              (512,1024,K=2048) x24
    for (int c = 0; c < 3; ++c)
        gemm_tf32<false,true,false,false,false,false><<<dim3(SEQ_/BN, IN_/BM, H_), 256>>>(
            hbuf + (long long)c*IN_*MID_, W2 + (long long)c*SEQ_*MID_,
            sq + (long long)c*IN_*SEQ_, nullptr,
            IN_, SEQ_, MID_,
            (long long)3*IN_*MID_, (long long)3*SEQ_*MID_, (long long)3*IN_*SEQ_);
    // 4. b[h] = k[h]^T @ q[h]                      (1024,1024,K=512) x8  (TN)
    gemm_tf32<true,false,false,false,false,false><<<dim3(SEQ_/BN, SEQ_/BM, H_), 256>>>(
        sq + (long long)IN_*SEQ_, sq, bmat, nullptr,
        SEQ_, SEQ_, IN_,
        (long long)3*IN_*SEQ_, (long long)3*IN_*SEQ_, (long long)SEQ_*SEQ_);
    // 5. att[h] = v[h] @ b[h]                      (512,1024,K=1024) x8
    gemm_tf32<false,false,false,false,false,false><<<dim3(SEQ_/BN, IN_/BM, H_), 256>>>(
        sq + (long long)2*IN_*SEQ_, bmat, att, nullptr,
        IN_, SEQ_, SEQ_,
        (long long)3*IN_*SEQ_, (long long)SEQ_*SEQ_, (long long)IN_*SEQ_);
    // 6. z1t = relu( cW1 @ relu(att_flat) )        (2048,1024,K=4096)
    gemm_tf32<false,false,false,true,true,false><<<dim3(SEQ_/BN, MID_/BM, 1), 256>>>(
        cW1, att, z1, nullptr, MID_, SEQ_, H_*IN_, 0, 0, 0);
    // 7. mout = cW2 @ relu(z1t)                    (512,1024,K=2048)
    gemm_tf32<false,false,false,true,false,false><<<dim3(SEQ_/BN, IN_/BM, 1), 256>>>(
        cW2, z1, mout, nullptr, IN_, SEQ_, MID_, 0, 0, 0);
}

static void launch_ffn(const float* x2, const float* Wa, const float* Wb,
                       float* t, float* out)
{
    // t = relu( Wa @ relu(x2) )                    (2048,1024,K=512)
    gemm_tf32<false,false,false,true,true,false><<<dim3(SEQ_/BN, MID_/BM, 1), 256>>>(
        Wa, x2, t, nullptr, MID_, SEQ_, IN_, 0, 0, 0);
    // out = Wb @ relu(t) + x2                      (512,1024,K=2048)
    gemm_tf32<false,false,false,true,false,true><<<dim3(SEQ_/BN, IN_/BM, 1), 256>>>(
        Wb, t, out, x2, IN_, SEQ_, MID_, 0, 0, 0);
}

extern "C" void kernel_launch(void* const* d_in, const int* in_sizes, int n_in,
                              void* d_out, int out_size)
{
    (void)in_sizes; (void)n_in; (void)out_size;

    const float* inp     = (const float*)d_in[0];
    const float* w_qkv_1 = (const float*)d_in[1];
    const float* w_qkv_2 = (const float*)d_in[2];
    const float* mh1_W1  = (const float*)d_in[3];
    const float* mh1_W2  = (const float*)d_in[4];
    const float* mh2_W1  = (const float*)d_in[5];
    const float* mh2_W2  = (const float*)d_in[6];
    const float* c1_W1   = (const float*)d_in[7];
    const float* c1_W2   = (const float*)d_in[8];
    const float* c2_W1   = (const float*)d_in[9];
    const float* c2_W2   = (const float*)d_in[10];
    const float* l1_W1   = (const float*)d_in[11];
    const float* l1_W2   = (const float*)d_in[12];
    const float* l2_W1   = (const float*)d_in[13];
    const float* l2_W2   = (const float*)d_in[14];
    const float* norm_w  = (const float*)d_in[15];
    const float* norm_b  = (const float*)d_in[16];
    float* out = (float*)d_out;

    float *qkv, *hbuf, *sq, *bmat, *att, *z1, *mout, *x1, *x2, *t;
    cudaGetSymbolAddress((void**)&qkv,  g_qkv);
    cudaGetSymbolAddress((void**)&hbuf, g_hbuf);
    cudaGetSymbolAddress((void**)&sq,   g_sq);
    cudaGetSymbolAddress((void**)&bmat, g_bmat);
    cudaGetSymbolAddress((void**)&att,  g_att);
    cudaGetSymbolAddress((void**)&z1,   g_z1);
    cudaGetSymbolAddress((void**)&mout, g_mout);
    cudaGetSymbolAddress((void**)&x1,   g_x1);
    cudaGetSymbolAddress((void**)&x2,   g_x2);
    cudaGetSymbolAddress((void**)&t,    g_t);

    // Block 1: x1 = LN(inp + MHA1(inp))
    launch_mha(inp, w_qkv_1, mh1_W1, mh1_W2, c1_W1, c1_W2,
               qkv, hbuf, sq, bmat, att, z1, mout);
    add_ln_kernel<<<IN_, 256>>>(inp, mout, norm_w, norm_b, x1);

    // Block 2: x2 = LN(inp + MHA2(x1))   (note: residual is inp, per reference)
    launch_mha(x1, w_qkv_2, mh2_W1, mh2_W2, c2_W1, c2_W2,
               qkv, hbuf, sq, bmat, att, z1, mout);
    add_ln_kernel<<<IN_, 256>>>(inp, mout, norm_w, norm_b, x2);

    // Two FFN heads
    launch_ffn(x2, l1_W1, l1_W2, t, out);
    launch_ffn(x2, l2_W1, l2_W2, t, out + (long long)IN_ * SEQ_);
}

// round 9
// speedup vs baseline: 1.3801x; 1.3792x over previous
#include <cuda_runtime.h>
#include <cstdint>

// Problem dims
#define H_   8
#define IN_  512
#define SEQ_ 1024
#define MID_ 2048

constexpr int BM = 128, BN = 128, BK = 16;
// Row stride for smem tiles. 136 mod 32 == 8, so fragment reads at
// addr = (kk+ac)*136 + (base + ar) hit bank (8*ac + ar + c) mod 32 — a
// bijection over the warp's 32 lanes -> conflict-free LDS (129 gave 4-way).
constexpr int SSTR = BM + 8;

// ---------------- scratch (device globals; no allocation allowed) ----------------
__device__ float g_qkv [3 * IN_ * SEQ_];          //  6 MB
__device__ float g_hbuf[H_ * 3 * IN_ * MID_];     // 96 MB
__device__ float g_sq  [H_ * 3 * IN_ * SEQ_];     // 48 MB
__device__ float g_bmat[H_ * SEQ_ * SEQ_];        // 32 MB
__device__ float g_att [H_ * IN_ * SEQ_];         // 16 MB
__device__ float g_z1  [MID_ * SEQ_];             //  8 MB
__device__ float g_mout[IN_ * SEQ_];
__device__ float g_x1  [IN_ * SEQ_];
__device__ float g_x2  [IN_ * SEQ_];
__device__ float g_t   [MID_ * SEQ_];             //  8 MB

// ---------------- tf32 helpers ----------------
__device__ __forceinline__ uint32_t f2tf32(float x) {
    uint32_t y;
    asm("cvt.rna.tf32.f32 %0, %1;" : "=r"(y) : "f"(x));
    return y;
}

__device__ __forceinline__ void mma_tf32(float c[4], const uint32_t a[4], const uint32_t b[2]) {
    asm volatile(
        "mma.sync.aligned.m16n8k8.row.col.f32.tf32.tf32.f32 "
        "{%0,%1,%2,%3}, {%4,%5,%6,%7}, {%8,%9}, {%0,%1,%2,%3};\n"
        : "+f"(c[0]), "+f"(c[1]), "+f"(c[2]), "+f"(c[3])
        : "r"(a[0]), "r"(a[1]), "r"(a[2]), "r"(a[3]), "r"(b[0]), "r"(b[1]));
}

// ---------------- generic batched GEMM: C = act( op(A) * op(B) [+ Res] ) ----------------
// A: !TA -> (M,K) row-major ; TA -> stored (K,M)
// B: !TB -> (K,N) row-major ; TB -> stored (N,K)
// C: (M,N) row-major. RA/RB: relu on A/B load. RO: relu on output. RES: C += Res.
// Batch offset: z -> (z/zdiv)*s?1 + (z%zdiv)*s?2   (lets one launch cover h x c).
// 3xTF32 split precision (hi*hi + lo*hi + hi*lo), fp32 accumulate.
// Register-prefetch pipeline: next k-tile's gmem loads overlap current compute.
template<bool TA, bool TB, bool RA, bool RB, bool RO, bool RES>
__global__ void __launch_bounds__(256)
gemm_tf32(const float* __restrict__ A, const float* __restrict__ B,
          float* __restrict__ C, const float* __restrict__ Res,
          int M, int N, int K,
          long long sA1, long long sA2,
          long long sB1, long long sB2,
          long long sC1, long long sC2, int zdiv)
{
    const int zz = blockIdx.z;
    const int zh = zz / zdiv;
    const int zc = zz - zh * zdiv;
    A += zh * sA1 + (long long)zc * sA2;
    B += zh * sB1 + (long long)zc * sB2;
    C += zh * sC1 + (long long)zc * sC2;

    const int bm = blockIdx.y * BM;
    const int bn = blockIdx.x * BN;

    __shared__ uint32_t AsHi[BK][SSTR];
    __shared__ uint32_t AsLo[BK][SSTR];
    __shared__ uint32_t BsHi[BK][SSTR];
    __shared__ uint32_t BsLo[BK][SSTR];

    const int tid  = threadIdx.x;
    const int lane = tid & 31;
    const int warp = tid >> 5;
    const int wm = (warp & 1) * 64;   // 2 warps along M
    const int wn = (warp >> 1) * 32;  // 4 warps along N
    const int ar = lane >> 2;         // mma group id
    const int ac = lane & 3;          // mma thread-in-group

    float acc[4][4][4];
#pragma unroll
    for (int i = 0; i < 4; ++i)
#pragma unroll
        for (int j = 0; j < 4; ++j)
#pragma unroll
            for (int r = 0; r < 4; ++r) acc[i][j][r] = 0.f;

    // -------- register prefetch buffers (one k-tile ahead) --------
    float pa[8], pb[8];

    auto ldg_tiles = [&](int k0) {
#pragma unroll
        for (int it = 0; it < 8; ++it) {
            int idx = tid + it * 256;
            long long gidx;
            if (!TA) gidx = (long long)(bm + (idx >> 4)) * K + (k0 + (idx & 15));
            else     gidx = (long long)(k0 + (idx >> 7)) * M + (bm + (idx & 127));
            float v = A[gidx];
            pa[it] = RA ? fmaxf(v, 0.f) : v;
        }
#pragma unroll
        for (int it = 0; it < 8; ++it) {
            int idx = tid + it * 256;
            long long gidx;
            if (!TB) gidx = (long long)(k0 + (idx >> 7)) * N + (bn + (idx & 127));
            else     gidx = (long long)(bn + (idx >> 4)) * K + (k0 + (idx & 15));
            float v = B[gidx];
            pb[it] = RB ? fmaxf(v, 0.f) : v;
        }
    };

    ldg_tiles(0);
    const int nk = K / BK;

    for (int t = 0; t < nk; ++t) {
        // ---- commit prefetched tile to smem (split hi/lo) ----
#pragma unroll
        for (int it = 0; it < 8; ++it) {
            int idx = tid + it * 256;
            int mm, kk;
            if (!TA) { mm = idx >> 4;  kk = idx & 15; }
            else     { kk = idx >> 7;  mm = idx & 127; }
            uint32_t hi = f2tf32(pa[it]);
            AsHi[kk][mm] = hi;
            AsLo[kk][mm] = f2tf32(pa[it] - __uint_as_float(hi));
        }
#pragma unroll
        for (int it = 0; it < 8; ++it) {
            int idx = tid + it * 256;
            int nn, kk;
            if (!TB) { kk = idx >> 7;  nn = idx & 127; }
            else     { nn = idx >> 4;  kk = idx & 15; }
            uint32_t hi = f2tf32(pb[it]);
            BsHi[kk][nn] = hi;
            BsLo[kk][nn] = f2tf32(pb[it] - __uint_as_float(hi));
        }
        __syncthreads();

        // issue next tile's global loads; latency hidden by the MMAs below
        if (t + 1 < nk) ldg_tiles((t + 1) * BK);

#pragma unroll
        for (int kk = 0; kk < BK; kk += 8) {
            uint32_t a[4][4], a2[4][4], b[4][2];
            // hi(A)
#pragma unroll
            for (int i = 0; i < 4; ++i) {
                int m0 = wm + i * 16 + ar;
                a[i][0] = AsHi[kk + ac][m0];
                a[i][1] = AsHi[kk + ac][m0 + 8];
                a[i][2] = AsHi[kk + ac + 4][m0];
                a[i][3] = AsHi[kk + ac + 4][m0 + 8];
            }
            // hi(B)
#pragma unroll
            for (int j = 0; j < 4; ++j) {
                int n0 = wn + j * 8 + ar;
                b[j][0] = BsHi[kk + ac][n0];
                b[j][1] = BsHi[kk + ac + 4][n0];
            }
            // hi*hi
#pragma unroll
            for (int i = 0; i < 4; ++i)
#pragma unroll
                for (int j = 0; j < 4; ++j) mma_tf32(acc[i][j], a[i], b[j]);
            // lo(A) * hi(B)
#pragma unroll
            for (int i = 0; i < 4; ++i) {
                int m0 = wm + i * 16 + ar;
                a2[i][0] = AsLo[kk + ac][m0];
                a2[i][1] = AsLo[kk + ac][m0 + 8];
                a2[i][2] = AsLo[kk + ac + 4][m0];
                a2[i][3] = AsLo[kk + ac + 4][m0 + 8];
            }
#pragma unroll
            for (int i = 0; i < 4; ++i)
#pragma unroll
                for (int j = 0; j < 4; ++j) mma_tf32(acc[i][j], a2[i], b[j]);
            // hi(A) * lo(B)
#pragma unroll
            for (int j = 0; j < 4; ++j) {
                int n0 = wn + j * 8 + ar;
                b[j][0] = BsLo[kk + ac][n0];
                b[j][1] = BsLo[kk + ac + 4][n0];
            }
#pragma unroll
            for (int i = 0; i < 4; ++i)
#pragma unroll
                for (int j = 0; j < 4; ++j) mma_tf32(acc[i][j], a[i], b[j]);
        }
        __syncthreads();
    }

    // ---- epilogue ----
#pragma unroll
    for (int i = 0; i < 4; ++i) {
        int m0 = bm + wm + i * 16 + ar;
#pragma unroll
        for (int j = 0; j < 4; ++j) {
            int n0 = bn + wn + j * 8 + ac * 2;
            long long o0 = (long long)m0 * N + n0;
            long long o1 = o0 + 8LL * N;
            float v0 = acc[i][j][0], v1 = acc[i][j][1];
            float v2 = acc[i][j][2], v3 = acc[i][j][3];
            if (RES) {
                v0 += Res[o0]; v1 += Res[o0 + 1];
                v2 += Res[o1]; v3 += Res[o1 + 1];
            }
            if (RO) {
                v0 = fmaxf(v0, 0.f); v1 = fmaxf(v1, 0.f);
                v2 = fmaxf(v2, 0.f); v3 = fmaxf(v3, 0.f);
            }
            C[o0] = v0; C[o0 + 1] = v1;
            C[o1] = v2; C[o1 + 1] = v3;
        }
    }
}

// ---------------- fused residual add + layernorm over last axis (1024) ----------------
__global__ void add_ln_kernel(const float* __restrict__ a, const float* __restrict__ b,
                              const float* __restrict__ w, const float* __restrict__ bias,
                              float* __restrict__ out)
{
    const int row = blockIdx.x;
    const int tid = threadIdx.x;
    const long long base = (long long)row * SEQ_;
    float v[4];
    float s = 0.f, ss = 0.f;
#pragma unroll
    for (int i = 0; i < 4; ++i) {
        int col = tid + i * 256;
        float t = a[base + col] + b[base + col];
        v[i] = t; s += t; ss += t * t;
    }
#pragma unroll
    for (int o = 16; o > 0; o >>= 1) {
        s  += __shfl_xor_sync(0xffffffffu, s,  o);
        ss += __shfl_xor_sync(0xffffffffu, ss, o);
    }
    __shared__ float rs[8], rss[8];
    if ((tid & 31) == 0) { rs[tid >> 5] = s; rss[tid >> 5] = ss; }
    __syncthreads();
    s = 0.f; ss = 0.f;
#pragma unroll
    for (int i = 0; i < 8; ++i) { s += rs[i]; ss += rss[i]; }
    const float mu  = s  * (1.0f / SEQ_);
    const float var = ss * (1.0f / SEQ_) - mu * mu;
    const float inv = rsqrtf(var + 1e-6f);
#pragma unroll
    for (int i = 0; i < 4; ++i) {
        int col = tid + i * 256;
        out[base + col] = (v[i] - mu) * inv * w[col] + bias[col];
    }
}

// ---------------- host orchestration ----------------
static void launch_mha(const float* x, const float* wqkv, const float* W1, const float* W2,
                       const float* cW1, const float* cW2,
                       float* qkv, float* hbuf, float* sq, float* bmat, float* att,
                       float* z1, float* mout)
{
    // 1. qkv[c] = w_qkv[c] @ x                     (512,1024,K=512) z=3
    gemm_tf32<false,false,false,false,false,false><<<dim3(SEQ_/BN, IN_/BM, 3), 256>>>(
        wqkv, x, qkv, nullptr, IN_, SEQ_, IN_,
        (long long)IN_*IN_, 0,  0, 0,  (long long)IN_*SEQ_, 0,  1);

    // 2. h[h,c] = relu( relu(qkv[c]) @ W1[h,c]^T ) (512,2048,K=1024) z=24 (h,c merged)
    gemm_tf32<false,true,true,false,true,false><<<dim3(MID_/BN, IN_/BM, H_*3), 256>>>(
        qkv, W1, hbuf, nullptr, IN_, MID_, SEQ_,
        0, (long long)IN_*SEQ_,
        (long long)3*MID_*SEQ_, (long long)MID_*SEQ_,
        (long long)3*IN_*MID_,  (long long)IN_*MID_,  3);

    // 3. sq[h,c] = h[h,c] @ W2[h,c]^T              (512,1024,K=2048) z=24 (h,c merged)
    gemm_tf32<false,true,false,false,false,false><<<dim3(SEQ_/BN, IN_/BM, H_*3), 256>>>(
        hbuf, W2, sq, nullptr, IN_, SEQ_, MID_,
        (long long)3*IN_*MID_,  (long long)IN_*MID_,
        (long long)3*SEQ_*MID_, (long long)SEQ_*MID_,
        (long long)3*IN_*SEQ_,  (long long)IN_*SEQ_,  3);

    // 4. b[h] = k[h]^T @ q[h]                      (1024,1024,K=512) z=8 (TN)
    gemm_tf32<true,false,false,false,false,false><<<dim3(SEQ_/BN, SEQ_/BM, H_), 256>>>(
        sq + (long long)IN_*SEQ_, sq, bmat, nullptr,
        SEQ_, SEQ_, IN_,
        (long long)3*IN_*SEQ_, 0,  (long long)3*IN_*SEQ_, 0,  (long long)SEQ_*SEQ_, 0,  1);

    // 5. att[h] = v[h] @ b[h]                      (512,1024,K=1024) z=8
    gemm_tf32<false,false,false,false,false,false><<<dim3(SEQ_/BN, IN_/BM, H_), 256>>>(
        sq + (long long)2*IN_*SEQ_, bmat, att, nullptr,
        IN_, SEQ_, SEQ_,
        (long long)3*IN_*SEQ_, 0,  (long long)SEQ_*SEQ_, 0,  (long long)IN_*SEQ_, 0,  1);

    // 6. z1t = relu( cW1 @ relu(att_flat) )        (2048,1024,K=4096)
    gemm_tf32<false,false,false,true,true,false><<<dim3(SEQ_/BN, MID_/BM, 1), 256>>>(
        cW1, att, z1, nullptr, MID_, SEQ_, H_*IN_, 0,0, 0,0, 0,0, 1);

    // 7. mout = cW2 @ relu(z1t)                    (512,1024,K=2048)
    gemm_tf32<false,false,false,true,false,false><<<dim3(SEQ_/BN, IN_/BM, 1), 256>>>(
        cW2, z1, mout, nullptr, IN_, SEQ_, MID_, 0,0, 0,0, 0,0, 1);
}

static void launch_ffn(const float* x2, const float* Wa, const float* Wb,
                       float* t, float* out)
{
    // t = relu( Wa @ relu(x2) )                    (2048,1024,K=512)
    gemm_tf32<false,false,false,true,true,false><<<dim3(SEQ_/BN, MID_/BM, 1), 256>>>(
        Wa, x2, t, nullptr, MID_, SEQ_, IN_, 0,0, 0,0, 0,0, 1);
    // out = Wb @ relu(t) + x2                      (512,1024,K=2048)
    gemm_tf32<false,false,false,true,false,true><<<dim3(SEQ_/BN, IN_/BM, 1), 256>>>(
        Wb, t, out, x2, IN_, SEQ_, MID_, 0,0, 0,0, 0,0, 1);
}

extern "C" void kernel_launch(void* const* d_in, const int* in_sizes, int n_in,
                              void* d_out, int out_size)
{
    (void)in_sizes; (void)n_in; (void)out_size;

    const float* inp     = (const float*)d_in[0];
    const float* w_qkv_1 = (const float*)d_in[1];
    const float* w_qkv_2 = (const float*)d_in[2];
    const float* mh1_W1  = (const float*)d_in[3];
    const float* mh1_W2  = (const float*)d_in[4];
    const float* mh2_W1  = (const float*)d_in[5];
    const float* mh2_W2  = (const float*)d_in[6];
    const float* c1_W1   = (const float*)d_in[7];
    const float* c1_W2   = (const float*)d_in[8];
    const float* c2_W1   = (const float*)d_in[9];
    const float* c2_W2   = (const float*)d_in[10];
    const float* l1_W1   = (const float*)d_in[11];
    const float* l1_W2   = (const float*)d_in[12];
    const float* l2_W1   = (const float*)d_in[13];
    const float* l2_W2   = (const float*)d_in[14];
    const float* norm_w  = (const float*)d_in[15];
    const float* norm_b  = (const float*)d_in[16];
    float* out = (float*)d_out;

    float *qkv, *hbuf, *sq, *bmat, *att, *z1, *mout, *x1, *x2, *t;
    cudaGetSymbolAddress((void**)&qkv,  g_qkv);
    cudaGetSymbolAddress((void**)&hbuf, g_hbuf);
    cudaGetSymbolAddress((void**)&sq,   g_sq);
    cudaGetSymbolAddress((void**)&bmat, g_bmat);
    cudaGetSymbolAddress((void**)&att,  g_att);
    cudaGetSymbolAddress((void**)&z1,   g_z1);
    cudaGetSymbolAddress((void**)&mout, g_mout);
    cudaGetSymbolAddress((void**)&x1,   g_x1);
    cudaGetSymbolAddress((void**)&x2,   g_x2);
    cudaGetSymbolAddress((void**)&t,    g_t);

    // Block 1: x1 = LN(inp + MHA1(inp))
    launch_mha(inp, w_qkv_1, mh1_W1, mh1_W2, c1_W1, c1_W2,
               qkv, hbuf, sq, bmat, att, z1, mout);
    add_ln_kernel<<<IN_, 256>>>(inp, mout, norm_w, norm_b, x1);

    // Block 2: x2 = LN(inp + MHA2(x1))   (residual is inp, per reference)
    launch_mha(x1, w_qkv_2, mh2_W1, mh2_W2, c2_W1, c2_W2,
               qkv, hbuf, sq, bmat, att, z1, mout);
    add_ln_kernel<<<IN_, 256>>>(inp, mout, norm_w, norm_b, x2);

    // Two FFN heads
    launch_ffn(x2, l1_W1, l1_W2, t, out);
    launch_ffn(x2, l2_W1, l2_W2, t, out + (long long)IN_ * SEQ_);
}

// round 10
// speedup vs baseline: 3.0054x; 2.1777x over previous
#include <cuda_runtime.h>
#include <cuda_bf16.h>
#include <cstdint>

// Problem dims
#define H_   8
#define IN_  512
#define SEQ_ 1024
#define MID_ 2048

constexpr int BM = 128, BN = 128, BK = 16;   // BK in k-elements (8 bf16 pairs)
// Stride (in uint32) for smem tiles: 136 mod 32 == 8 -> fragment reads at
// addr = (ac)*136 + (base+ar) hit bank (8*ac + ar) mod 32, a bijection over
// the warp -> conflict-free LDS.
constexpr int SSTR = BM + 8;

// ---------------- scratch (device globals; no allocation allowed) ----------------
__device__ float g_qkv [3 * IN_ * SEQ_];          //  6 MB
__device__ float g_hbuf[H_ * 3 * IN_ * MID_];     // 96 MB
__device__ float g_sq  [H_ * 3 * IN_ * SEQ_];     // 48 MB
__device__ float g_bmat[H_ * SEQ_ * SEQ_];        // 32 MB
__device__ float g_att [H_ * IN_ * SEQ_];         // 16 MB
__device__ float g_z1  [MID_ * SEQ_];             //  8 MB
__device__ float g_mout[IN_ * SEQ_];
__device__ float g_x1  [IN_ * SEQ_];
__device__ float g_x2  [IN_ * SEQ_];
__device__ float g_t   [MID_ * SEQ_];             //  8 MB

// ---------------- bf16 helpers ----------------
__device__ __forceinline__ uint32_t pack2(__nv_bfloat162 h) {
    return *reinterpret_cast<uint32_t*>(&h);
}

__device__ __forceinline__ void mma_bf16(float c[4], const uint32_t a[4], const uint32_t b[2]) {
    asm volatile(
        "mma.sync.aligned.m16n8k16.row.col.f32.bf16.bf16.f32 "
        "{%0,%1,%2,%3}, {%4,%5,%6,%7}, {%8,%9}, {%0,%1,%2,%3};\n"
        : "+f"(c[0]), "+f"(c[1]), "+f"(c[2]), "+f"(c[3])
        : "r"(a[0]), "r"(a[1]), "r"(a[2]), "r"(a[3]), "r"(b[0]), "r"(b[1]));
}

// ---------------- generic batched GEMM: C = act( op(A) * op(B) [+ Res] ) ----------------
// A: !TA -> (M,K) row-major ; TA -> stored (K,M)
// B: !TB -> (K,N) row-major ; TB -> stored (N,K)
// C: (M,N) row-major. RA/RB relu on load; RO relu on output; RES: C += Res.
// Batch offset: z -> (z/zdiv)*s?1 + (z%zdiv)*s?2.
// 3-term bf16 split precision: v = hi + lo (both bf16); hi*hi + lo*hi + hi*lo,
// fp32 accumulate via tensor cores. Double-buffered smem, reg-prefetch pipeline.
template<bool TA, bool TB, bool RA, bool RB, bool RO, bool RES>
__global__ void __launch_bounds__(256, 2)
gemm_bf16x3(const float* __restrict__ A, const float* __restrict__ B,
            float* __restrict__ C, const float* __restrict__ Res,
            int M, int N, int K,
            long long sA1, long long sA2,
            long long sB1, long long sB2,
            long long sC1, long long sC2, int zdiv)
{
    const int zz = blockIdx.z;
    const int zh = zz / zdiv;
    const int zc = zz - zh * zdiv;
    A += zh * sA1 + (long long)zc * sA2;
    B += zh * sB1 + (long long)zc * sB2;
    C += zh * sC1 + (long long)zc * sC2;

    const int bm = blockIdx.y * BM;
    const int bn = blockIdx.x * BN;

    // [stage][k-pair][row], packed bf16x2 (2 consecutive k per word)
    __shared__ uint32_t AsHi[2][8][SSTR];
    __shared__ uint32_t AsLo[2][8][SSTR];
    __shared__ uint32_t BsHi[2][8][SSTR];
    __shared__ uint32_t BsLo[2][8][SSTR];

    const int tid  = threadIdx.x;
    const int lane = tid & 31;
    const int warp = tid >> 5;
    const int wm = (warp & 1) * 64;   // 2 warps along M
    const int wn = (warp >> 1) * 32;  // 4 warps along N
    const int ar = lane >> 2;         // mma group id (row/col within tile)
    const int ac = lane & 3;          // mma thread-in-group (k-pair index)

    float acc[4][4][4];
#pragma unroll
    for (int i = 0; i < 4; ++i)
#pragma unroll
        for (int j = 0; j < 4; ++j)
#pragma unroll
            for (int r = 0; r < 4; ++r) acc[i][j][r] = 0.f;

    // -------- register prefetch (one k-tile ahead): 4 pairs per operand --------
    float2 pa[4], pb[4];

    auto ldgA = [&](int k0) {
#pragma unroll
        for (int it = 0; it < 4; ++it) {
            int p = tid + it * 256;
            float2 v;
            if (!TA) {
                int m = p >> 3, k2 = p & 7;
                v = *reinterpret_cast<const float2*>(A + (long long)(bm + m) * K + (k0 + 2 * k2));
            } else {
                int k2 = p >> 7, m = p & 127;
                const float* a0 = A + (long long)(k0 + 2 * k2) * M + (bm + m);
                v.x = a0[0]; v.y = a0[M];
            }
            if (RA) { v.x = fmaxf(v.x, 0.f); v.y = fmaxf(v.y, 0.f); }
            pa[it] = v;
        }
    };
    auto ldgB = [&](int k0) {
#pragma unroll
        for (int it = 0; it < 4; ++it) {
            int p = tid + it * 256;
            float2 v;
            if (!TB) {
                int k2 = p >> 7, n = p & 127;
                const float* b0 = B + (long long)(k0 + 2 * k2) * N + (bn + n);
                v.x = b0[0]; v.y = b0[N];
            } else {
                int n = p >> 3, k2 = p & 7;
                v = *reinterpret_cast<const float2*>(B + (long long)(bn + n) * K + (k0 + 2 * k2));
            }
            if (RB) { v.x = fmaxf(v.x, 0.f); v.y = fmaxf(v.y, 0.f); }
            pb[it] = v;
        }
    };

    auto commit = [&](int s) {
#pragma unroll
        for (int it = 0; it < 4; ++it) {
            int p = tid + it * 256;
            int m, k2;
            if (!TA) { m = p >> 3; k2 = p & 7; }
            else     { k2 = p >> 7; m = p & 127; }
            float2 v = pa[it];
            __nv_bfloat162 h = __floats2bfloat162_rn(v.x, v.y);        // low half = even k
            float2 r;
            r.x = v.x - __bfloat162float(h.x);
            r.y = v.y - __bfloat162float(h.y);
            __nv_bfloat162 l = __floats2bfloat162_rn(r.x, r.y);
            AsHi[s][k2][m] = pack2(h);
            AsLo[s][k2][m] = pack2(l);
        }
#pragma unroll
        for (int it = 0; it < 4; ++it) {
            int p = tid + it * 256;
            int n, k2;
            if (!TB) { k2 = p >> 7; n = p & 127; }
            else     { n = p >> 3; k2 = p & 7; }
            float2 v = pb[it];
            __nv_bfloat162 h = __floats2bfloat162_rn(v.x, v.y);
            float2 r;
            r.x = v.x - __bfloat162float(h.x);
            r.y = v.y - __bfloat162float(h.y);
            __nv_bfloat162 l = __floats2bfloat162_rn(r.x, r.y);
            BsHi[s][k2][n] = pack2(h);
            BsLo[s][k2][n] = pack2(l);
        }
    };

    ldgA(0); ldgB(0);
    const int nk = K / BK;

    for (int t = 0; t < nk; ++t) {
        const int s = t & 1;
        commit(s);                               // STS current tile (from prefetch regs)
        if (t + 1 < nk) { ldgA((t + 1) * BK); ldgB((t + 1) * BK); }  // LDG next tile
        __syncthreads();                         // single barrier per tile (ping-pong bufs)

        uint32_t ah[4][4], al[4][4], bb[4][2];
        // A hi + lo fragments (one k16 step per tile)
#pragma unroll
        for (int i = 0; i < 4; ++i) {
            int m0 = wm + i * 16 + ar;
            ah[i][0] = AsHi[s][ac][m0];
            ah[i][1] = AsHi[s][ac][m0 + 8];
            ah[i][2] = AsHi[s][ac + 4][m0];
            ah[i][3] = AsHi[s][ac + 4][m0 + 8];
            al[i][0] = AsLo[s][ac][m0];
            al[i][1] = AsLo[s][ac][m0 + 8];
            al[i][2] = AsLo[s][ac + 4][m0];
            al[i][3] = AsLo[s][ac + 4][m0 + 8];
        }
        // B hi fragments
#pragma unroll
        for (int j = 0; j < 4; ++j) {
            int n0 = wn + j * 8 + ar;
            bb[j][0] = BsHi[s][ac][n0];
            bb[j][1] = BsHi[s][ac + 4][n0];
        }
        // pass 1: hi*hi
#pragma unroll
        for (int i = 0; i < 4; ++i)
#pragma unroll
            for (int j = 0; j < 4; ++j) mma_bf16(acc[i][j], ah[i], bb[j]);
        // pass 2: lo*hi
#pragma unroll
        for (int i = 0; i < 4; ++i)
#pragma unroll
            for (int j = 0; j < 4; ++j) mma_bf16(acc[i][j], al[i], bb[j]);
        // pass 3: hi*lo (overwrite bb with B-lo)
#pragma unroll
        for (int j = 0; j < 4; ++j) {
            int n0 = wn + j * 8 + ar;
            bb[j][0] = BsLo[s][ac][n0];
            bb[j][1] = BsLo[s][ac + 4][n0];
        }
#pragma unroll
        for (int i = 0; i < 4; ++i)
#pragma unroll
            for (int j = 0; j < 4; ++j) mma_bf16(acc[i][j], ah[i], bb[j]);
    }

    // ---- epilogue ----
#pragma unroll
    for (int i = 0; i < 4; ++i) {
        int m0 = bm + wm + i * 16 + ar;
#pragma unroll
        for (int j = 0; j < 4; ++j) {
            int n0 = bn + wn + j * 8 + ac * 2;
            long long o0 = (long long)m0 * N + n0;
            long long o1 = o0 + 8LL * N;
            float v0 = acc[i][j][0], v1 = acc[i][j][1];
            float v2 = acc[i][j][2], v3 = acc[i][j][3];
            if (RES) {
                v0 += Res[o0]; v1 += Res[o0 + 1];
                v2 += Res[o1]; v3 += Res[o1 + 1];
            }
            if (RO) {
                v0 = fmaxf(v0, 0.f); v1 = fmaxf(v1, 0.f);
                v2 = fmaxf(v2, 0.f); v3 = fmaxf(v3, 0.f);
            }
            C[o0] = v0; C[o0 + 1] = v1;
            C[o1] = v2; C[o1 + 1] = v3;
        }
    }
}

// ---------------- fused residual add + layernorm over last axis (1024) ----------------
__global__ void add_ln_kernel(const float* __restrict__ a, const float* __restrict__ b,
                              const float* __restrict__ w, const float* __restrict__ bias,
                              float* __restrict__ out)
{
    const int row = blockIdx.x;
    const int tid = threadIdx.x;
    const long long base = (long long)row * SEQ_;
    float v[4];
    float s = 0.f, ss = 0.f;
#pragma unroll
    for (int i = 0; i < 4; ++i) {
        int col = tid + i * 256;
        float t = a[base + col] + b[base + col];
        v[i] = t; s += t; ss += t * t;
    }
#pragma unroll
    for (int o = 16; o > 0; o >>= 1) {
        s  += __shfl_xor_sync(0xffffffffu, s,  o);
        ss += __shfl_xor_sync(0xffffffffu, ss, o);
    }
    __shared__ float rs[8], rss[8];
    if ((tid & 31) == 0) { rs[tid >> 5] = s; rss[tid >> 5] = ss; }
    __syncthreads();
    s = 0.f; ss = 0.f;
#pragma unroll
    for (int i = 0; i < 8; ++i) { s += rs[i]; ss += rss[i]; }
    const float mu  = s  * (1.0f / SEQ_);
    const float var = ss * (1.0f / SEQ_) - mu * mu;
    const float inv = rsqrtf(var + 1e-6f);
#pragma unroll
    for (int i = 0; i < 4; ++i) {
        int col = tid + i * 256;
        out[base + col] = (v[i] - mu) * inv * w[col] + bias[col];
    }
}

// ---------------- host orchestration ----------------
static void launch_mha(const float* x, const float* wqkv, const float* W1, const float* W2,
                       const float* cW1, const float* cW2,
                       float* qkv, float* hbuf, float* sq, float* bmat, float* att,
                       float* z1, float* mout)
{
    // 1. qkv[c] = w_qkv[c] @ x                     (512,1024,K=512) z=3
    gemm_bf16x3<false,false,false,false,false,false><<<dim3(SEQ_/BN, IN_/BM, 3), 256>>>(
        wqkv, x, qkv, nullptr, IN_, SEQ_, IN_,
        (long long)IN_*IN_, 0,  0, 0,  (long long)IN_*SEQ_, 0,  1);

    // 2. h[h,c] = relu( relu(qkv[c]) @ W1[h,c]^T ) (512,2048,K=1024) z=24 (h,c merged)
    gemm_bf16x3<false,true,true,false,true,false><<<dim3(MID_/BN, IN_/BM, H_*3), 256>>>(
        qkv, W1, hbuf, nullptr, IN_, MID_, SEQ_,
        0, (long long)IN_*SEQ_,
        (long long)3*MID_*SEQ_, (long long)MID_*SEQ_,
        (long long)3*IN_*MID_,  (long long)IN_*MID_,  3);

    // 3. sq[h,c] = h[h,c] @ W2[h,c]^T              (512,1024,K=2048) z=24 (h,c merged)
    gemm_bf16x3<false,true,false,false,false,false><<<dim3(SEQ_/BN, IN_/BM, H_*3), 256>>>(
        hbuf, W2, sq, nullptr, IN_, SEQ_, MID_,
        (long long)3*IN_*MID_,  (long long)IN_*MID_,
        (long long)3*SEQ_*MID_, (long long)SEQ_*MID_,
        (long long)3*IN_*SEQ_,  (long long)IN_*SEQ_,  3);

    // 4. b[h] = k[h]^T @ q[h]                      (1024,1024,K=512) z=8 (TN)
    gemm_bf16x3<true,false,false,false,false,false><<<dim3(SEQ_/BN, SEQ_/BM, H_), 256>>>(
        sq + (long long)IN_*SEQ_, sq, bmat, nullptr,
        SEQ_, SEQ_, IN_,
        (long long)3*IN_*SEQ_, 0,  (long long)3*IN_*SEQ_, 0,  (long long)SEQ_*SEQ_, 0,  1);

    // 5. att[h] = v[h] @ b[h]                      (512,1024,K=1024) z=8
    gemm_bf16x3<false,false,false,false,false,false><<<dim3(SEQ_/BN, IN_/BM, H_), 256>>>(
        sq + (long long)2*IN_*SEQ_, bmat, att, nullptr,
        IN_, SEQ_, SEQ_,
        (long long)3*IN_*SEQ_, 0,  (long long)SEQ_*SEQ_, 0,  (long long)IN_*SEQ_, 0,  1);

    // 6. z1t = relu( cW1 @ relu(att_flat) )        (2048,1024,K=4096)
    gemm_bf16x3<false,false,false,true,true,false><<<dim3(SEQ_/BN, MID_/BM, 1), 256>>>(
        cW1, att, z1, nullptr, MID_, SEQ_, H_*IN_, 0,0, 0,0, 0,0, 1);

    // 7. mout = cW2 @ relu(z1t)                    (512,1024,K=2048)
    gemm_bf16x3<false,false,false,true,false,false><<<dim3(SEQ_/BN, IN_/BM, 1), 256>>>(
        cW2, z1, mout, nullptr, IN_, SEQ_, MID_, 0,0, 0,0, 0,0, 1);
}

static void launch_ffn(const float* x2, const float* Wa, const float* Wb,
                       float* t, float* out)
{
    // t = relu( Wa @ relu(x2) )                    (2048,1024,K=512)
    gemm_bf16x3<false,false,false,true,true,false><<<dim3(SEQ_/BN, MID_/BM, 1), 256>>>(
        Wa, x2, t, nullptr, MID_, SEQ_, IN_, 0,0, 0,0, 0,0, 1);
    // out = Wb @ relu(t) + x2                      (512,1024,K=2048)
    gemm_bf16x3<false,false,false,true,false,true><<<dim3(SEQ_/BN, IN_/BM, 1), 256>>>(
        Wb, t, out, x2, IN_, SEQ_, MID_, 0,0, 0,0, 0,0, 1);
}

extern "C" void kernel_launch(void* const* d_in, const int* in_sizes, int n_in,
                              void* d_out, int out_size)
{
    (void)in_sizes; (void)n_in; (void)out_size;

    const float* inp     = (const float*)d_in[0];
    const float* w_qkv_1 = (const float*)d_in[1];
    const float* w_qkv_2 = (const float*)d_in[2];
    const float* mh1_W1  = (const float*)d_in[3];
    const float* mh1_W2  = (const float*)d_in[4];
    const float* mh2_W1  = (const float*)d_in[5];
    const float* mh2_W2  = (const float*)d_in[6];
    const float* c1_W1   = (const float*)d_in[7];
    const float* c1_W2   = (const float*)d_in[8];
    const float* c2_W1   = (const float*)d_in[9];
    const float* c2_W2   = (const float*)d_in[10];
    const float* l1_W1   = (const float*)d_in[11];
    const float* l1_W2   = (const float*)d_in[12];
    const float* l2_W1   = (const float*)d_in[13];
    const float* l2_W2   = (const float*)d_in[14];
    const float* norm_w  = (const float*)d_in[15];
    const float* norm_b  = (const float*)d_in[16];
    float* out = (float*)d_out;

    float *qkv, *hbuf, *sq, *bmat, *att, *z1, *mout, *x1, *x2, *t;
    cudaGetSymbolAddress((void**)&qkv,  g_qkv);
    cudaGetSymbolAddress((void**)&hbuf, g_hbuf);
    cudaGetSymbolAddress((void**)&sq,   g_sq);
    cudaGetSymbolAddress((void**)&bmat, g_bmat);
    cudaGetSymbolAddress((void**)&att,  g_att);
    cudaGetSymbolAddress((void**)&z1,   g_z1);
    cudaGetSymbolAddress((void**)&mout, g_mout);
    cudaGetSymbolAddress((void**)&x1,   g_x1);
    cudaGetSymbolAddress((void**)&x2,   g_x2);
    cudaGetSymbolAddress((void**)&t,    g_t);

    // Block 1: x1 = LN(inp + MHA1(inp))
    launch_mha(inp, w_qkv_1, mh1_W1, mh1_W2, c1_W1, c1_W2,
               qkv, hbuf, sq, bmat, att, z1, mout);
    add_ln_kernel<<<IN_, 256>>>(inp, mout, norm_w, norm_b, x1);

    // Block 2: x2 = LN(inp + MHA2(x1))   (residual is inp, per reference)
    launch_mha(x1, w_qkv_2, mh2_W1, mh2_W2, c2_W1, c2_W2,
               qkv, hbuf, sq, bmat, att, z1, mout);
    add_ln_kernel<<<IN_, 256>>>(inp, mout, norm_w, norm_b, x2);

    // Two FFN heads
    launch_ffn(x2, l1_W1, l1_W2, t, out);
    launch_ffn(x2, l2_W1, l2_W2, t, out + (long long)IN_ * SEQ_);
}

// round 12
// speedup vs baseline: 3.6696x; 1.2210x over previous
#include <cuda_runtime.h>
#include <cuda_bf16.h>
#include <cstdint>

// Problem dims
#define H_   8
#define IN_  512
#define SEQ_ 1024
#define MID_ 2048

// ---------------- HMMA GEMM tile config ----------------
constexpr int BM = 128, BN = 128, BK = 32;     // BK in bf16 k-elements per stage
constexpr int RSB = 80;                        // smem row stride bytes (64 data + 16 pad)
                                               // LDSM banks: 20*r mod 32 -> {0,20,8,28,16,4,24,12} all distinct
constexpr int OPB = 128 * RSB;                 // bytes per operand-half tile (10240)
constexpr int OFF_AHI = 0, OFF_ALO = OPB, OFF_BHI = 2 * OPB, OFF_BLO = 3 * OPB;
constexpr int STAGE = 4 * OPB;                 // 40960
constexpr int GSMEM = 2 * STAGE;               // 81920 bytes dynamic smem

// ---------------- scratch (device globals; no allocation allowed) ----------------
__device__ float g_sq  [H_ * 3 * IN_ * SEQ_];
__device__ float g_att [H_ * IN_ * SEQ_];
__device__ float g_z1  [MID_ * SEQ_];
__device__ float g_mout[IN_ * SEQ_];
__device__ float g_x1  [IN_ * SEQ_];
__device__ float g_x2  [IN_ * SEQ_];
__device__ float g_t   [MID_ * SEQ_];
// pre-split bf16 hi/lo operand buffers
__device__ __nv_bfloat16 g_wqS_h [3 * IN_ * IN_],        g_wqS_l [3 * IN_ * IN_];
__device__ __nv_bfloat16 g_xT_h  [SEQ_ * IN_],           g_xT_l  [SEQ_ * IN_];
__device__ __nv_bfloat16 g_qkvS_h[3 * IN_ * SEQ_],       g_qkvS_l[3 * IN_ * SEQ_];
__device__ __nv_bfloat16 g_W1S_h [H_ * 3 * MID_ * SEQ_], g_W1S_l [H_ * 3 * MID_ * SEQ_];
__device__ __nv_bfloat16 g_W2S_h [H_ * 3 * SEQ_ * MID_], g_W2S_l [H_ * 3 * SEQ_ * MID_];
__device__ __nv_bfloat16 g_hbS_h [H_ * 3 * IN_ * MID_],  g_hbS_l [H_ * 3 * IN_ * MID_];
__device__ __nv_bfloat16 g_qT_h  [H_ * SEQ_ * IN_],      g_qT_l  [H_ * SEQ_ * IN_];
__device__ __nv_bfloat16 g_kT_h  [H_ * SEQ_ * IN_],      g_kT_l  [H_ * SEQ_ * IN_];
__device__ __nv_bfloat16 g_vS_h  [H_ * IN_ * SEQ_],      g_vS_l  [H_ * IN_ * SEQ_];
__device__ __nv_bfloat16 g_bTS_h [H_ * SEQ_ * SEQ_],     g_bTS_l [H_ * SEQ_ * SEQ_];
__device__ __nv_bfloat16 g_aT_h  [SEQ_ * H_ * IN_],      g_aT_l  [SEQ_ * H_ * IN_];
__device__ __nv_bfloat16 g_zT_h  [SEQ_ * MID_],          g_zT_l  [SEQ_ * MID_];
__device__ __nv_bfloat16 g_cW1S_h[MID_ * H_ * IN_],      g_cW1S_l[MID_ * H_ * IN_];
__device__ __nv_bfloat16 g_cW2S_h[IN_ * MID_],           g_cW2S_l[IN_ * MID_];
__device__ __nv_bfloat16 g_WaS_h [MID_ * IN_],           g_WaS_l [MID_ * IN_];
__device__ __nv_bfloat16 g_WbS_h [IN_ * MID_],           g_WbS_l [IN_ * MID_];

// ---------------- PTX helpers ----------------
__device__ __forceinline__ uint32_t smem_u32(const void* p) {
    uint32_t a;
    asm("{ .reg .u64 t; cvta.to.shared.u64 t, %1; cvt.u32.u64 %0, t; }" : "=r"(a) : "l"(p));
    return a;
}
__device__ __forceinline__ void cpa16(uint32_t d, const void* s) {
    asm volatile("cp.async.cg.shared.global [%0], [%1], 16;" :: "r"(d), "l"(s));
}
__device__ __forceinline__ void cp_commit() {
    asm volatile("cp.async.commit_group;" ::: "memory");
}
template<int N> __device__ __forceinline__ void cp_wait() {
    asm volatile("cp.async.wait_group %0;" :: "n"(N) : "memory");
}
__device__ __forceinline__ void ldsm4(uint32_t& r0, uint32_t& r1, uint32_t& r2, uint32_t& r3, uint32_t a) {
    asm volatile("ldmatrix.sync.aligned.m8n8.x4.shared.b16 {%0,%1,%2,%3}, [%4];"
                 : "=r"(r0), "=r"(r1), "=r"(r2), "=r"(r3) : "r"(a));
}
__device__ __forceinline__ void mma_bf16(float c[4], const uint32_t a[4], const uint32_t b[2]) {
    asm volatile(
        "mma.sync.aligned.m16n8k16.row.col.f32.bf16.bf16.f32 "
        "{%0,%1,%2,%3}, {%4,%5,%6,%7}, {%8,%9}, {%0,%1,%2,%3};\n"
        : "+f"(c[0]), "+f"(c[1]), "+f"(c[2]), "+f"(c[3])
        : "r"(a[0]), "r"(a[1]), "r"(a[2]), "r"(a[3]), "r"(b[0]), "r"(b[1]));
}
__device__ __forceinline__ uint32_t pack2(__nv_bfloat162 h) {
    return *reinterpret_cast<uint32_t*>(&h);
}

// ---------------- GEMM: C = act( A * B^T [+Res] ), all operands pre-split bf16 ----------------
// A (M,K) row-major hi/lo; B (N,K) row-major hi/lo. 3-pass split: hi*hi + hi*lo + lo*hi (fp32 acc).
// OM=0: C fp32 (optional RO relu, RES residual). OM=1: C written as bf16 hi/lo split (optional RO).
// z -> (z/zdiv)*s?1 + (z%zdiv)*s?2 batch offsets.
template<bool RO, bool RES, int OM>
__global__ void __launch_bounds__(256, 2)
gemm_hmma(const __nv_bfloat16* __restrict__ Ah, const __nv_bfloat16* __restrict__ Al,
          const __nv_bfloat16* __restrict__ Bh, const __nv_bfloat16* __restrict__ Bl,
          float* __restrict__ Cf, __nv_bfloat16* __restrict__ Coh, __nv_bfloat16* __restrict__ Col,
          const float* __restrict__ Res,
          int M, int N, int K,
          long long sA1, long long sA2, long long sB1, long long sB2,
          long long sC1, long long sC2, int zdiv)
{
    extern __shared__ char smem[];
    const int tid = threadIdx.x, lane = tid & 31, warp = tid >> 5;

    const int zz = blockIdx.z, zh = zz / zdiv, zc = zz - zh * zdiv;
    const long long offA = zh * sA1 + (long long)zc * sA2;
    const long long offB = zh * sB1 + (long long)zc * sB2;
    const long long cOff = zh * sC1 + (long long)zc * sC2;

    const int bm = blockIdx.y * BM, bn = blockIdx.x * BN;
    const uint32_t sb = smem_u32(smem);

    // staging mapping: 256 threads x 2 rows, 4 k-quads of 16B per row
    const int srow = tid >> 2, skq = tid & 3;
    const __nv_bfloat16* pAh = Ah + offA + (long long)(bm + srow) * K + skq * 8;
    const __nv_bfloat16* pAl = Al + offA + (long long)(bm + srow) * K + skq * 8;
    const __nv_bfloat16* pBh = Bh + offB + (long long)(bn + srow) * K + skq * 8;
    const __nv_bfloat16* pBl = Bl + offB + (long long)(bn + srow) * K + skq * 8;
    const long long rstep = 64LL * K;
    const uint32_t sdst = srow * RSB + skq * 16;

    auto stage_load = [&](int t) {
        const int k0 = t * BK;
        const uint32_t d = sb + (t & 1) * STAGE + sdst;
        cpa16(d + OFF_AHI,            pAh + k0);
        cpa16(d + OFF_AHI + 64 * RSB, pAh + k0 + rstep);
        cpa16(d + OFF_ALO,            pAl + k0);
        cpa16(d + OFF_ALO + 64 * RSB, pAl + k0 + rstep);
        cpa16(d + OFF_BHI,            pBh + k0);
        cpa16(d + OFF_BHI + 64 * RSB, pBh + k0 + rstep);
        cpa16(d + OFF_BLO,            pBl + k0);
        cpa16(d + OFF_BLO + 64 * RSB, pBl + k0 + rstep);
        cp_commit();
    };

    float acc[4][4][4];
#pragma unroll
    for (int i = 0; i < 4; ++i)
#pragma unroll
        for (int j = 0; j < 4; ++j)
#pragma unroll
            for (int r = 0; r < 4; ++r) acc[i][j][r] = 0.f;

    // warp tiling: 2 warps M x 4 warps N; warp tile 64x32
    const int wm = (warp & 1) * 64, wn = (warp >> 1) * 32;
    // ldmatrix lane address components (A: x4 = {m0k0, m8k0, m0k8, m8k8})
    const int aRow   = wm + (lane & 7) + ((lane >> 3) & 1) * 8;   // + i*16
    const int aChunk = (lane >> 4) * 16;
    // B: x4 = {n0k0, n0k8, n8k0, n8k8}
    const int bRow   = wn + (lane & 7) + (lane >> 4) * 8;          // + jj*16
    const int bChunk = ((lane >> 3) & 1) * 16;

    stage_load(0);
    const int nk = K / BK;

    for (int t = 0; t < nk; ++t) {
        if (t + 1 < nk) { stage_load(t + 1); cp_wait<1>(); }
        else            { cp_wait<0>(); }
        __syncthreads();

        const uint32_t ss = sb + (t & 1) * STAGE;
#pragma unroll
        for (int kk = 0; kk < 2; ++kk) {
            const uint32_t kb = kk * 32;
            uint32_t ah[4][4], bh2[4][2], bl2[4][2];
            // A-hi fragments
#pragma unroll
            for (int i = 0; i < 4; ++i)
                ldsm4(ah[i][0], ah[i][1], ah[i][2], ah[i][3],
                      ss + OFF_AHI + (aRow + i * 16) * RSB + kb + aChunk);
            // B-hi fragments
#pragma unroll
            for (int jj = 0; jj < 2; ++jj) {
                uint32_t r0, r1, r2, r3;
                ldsm4(r0, r1, r2, r3, ss + OFF_BHI + (bRow + jj * 16) * RSB + kb + bChunk);
                bh2[2 * jj][0] = r0; bh2[2 * jj][1] = r1;
                bh2[2 * jj + 1][0] = r2; bh2[2 * jj + 1][1] = r3;
            }
            // pass 1: hi*hi
#pragma unroll
            for (int i = 0; i < 4; ++i)
#pragma unroll
                for (int j = 0; j < 4; ++j) mma_bf16(acc[i][j], ah[i], bh2[j]);
            // B-lo fragments, pass 2: hi*lo
#pragma unroll
            for (int jj = 0; jj < 2; ++jj) {
                uint32_t r0, r1, r2, r3;
                ldsm4(r0, r1, r2, r3, ss + OFF_BLO + (bRow + jj * 16) * RSB + kb + bChunk);
                bl2[2 * jj][0] = r0; bl2[2 * jj][1] = r1;
                bl2[2 * jj + 1][0] = r2; bl2[2 * jj + 1][1] = r3;
            }
#pragma unroll
            for (int i = 0; i < 4; ++i)
#pragma unroll
                for (int j = 0; j < 4; ++j) mma_bf16(acc[i][j], ah[i], bl2[j]);
            // A-lo fragments (reuse ah regs), pass 3: lo*hi
#pragma unroll
            for (int i = 0; i < 4; ++i)
                ldsm4(ah[i][0], ah[i][1], ah[i][2], ah[i][3],
                      ss + OFF_ALO + (aRow + i * 16) * RSB + kb + aChunk);
#pragma unroll
            for (int i = 0; i < 4; ++i)
#pragma unroll
                for (int j = 0; j < 4; ++j) mma_bf16(acc[i][j], ah[i], bh2[j]);
        }
        __syncthreads();
    }

    // ---- epilogue ----
    const int ar = lane >> 2, ac = lane & 3;
#pragma unroll
    for (int i = 0; i < 4; ++i) {
        int m0 = bm + wm + i * 16 + ar;
#pragma unroll
        for (int j = 0; j < 4; ++j) {
            int n0 = bn + wn + j * 8 + ac * 2;
            long long o0 = cOff + (long long)m0 * N + n0;
            long long o1 = o0 + 8LL * N;
            float v0 = acc[i][j][0], v1 = acc[i][j][1];
            float v2 = acc[i][j][2], v3 = acc[i][j][3];
            if (RES) {
                v0 += Res[o0]; v1 += Res[o0 + 1];
                v2 += Res[o1]; v3 += Res[o1 + 1];
            }
            if (RO) {
                v0 = fmaxf(v0, 0.f); v1 = fmaxf(v1, 0.f);
                v2 = fmaxf(v2, 0.f); v3 = fmaxf(v3, 0.f);
            }
            if (OM == 0) {
                *reinterpret_cast<float2*>(Cf + o0) = make_float2(v0, v1);
                *reinterpret_cast<float2*>(Cf + o1) = make_float2(v2, v3);
            } else {
                __nv_bfloat162 h0 = __floats2bfloat162_rn(v0, v1);
                __nv_bfloat162 l0 = __floats2bfloat162_rn(v0 - __bfloat162float(h0.x),
                                                          v1 - __bfloat162float(h0.y));
                __nv_bfloat162 h1 = __floats2bfloat162_rn(v2, v3);
                __nv_bfloat162 l1 = __floats2bfloat162_rn(v2 - __bfloat162float(h1.x),
                                                          v3 - __bfloat162float(h1.y));
                reinterpret_cast<__nv_bfloat162*>(Coh)[o0 >> 1] = h0;
                reinterpret_cast<__nv_bfloat162*>(Col)[o0 >> 1] = l0;
                reinterpret_cast<__nv_bfloat162*>(Coh)[o1 >> 1] = h1;
                reinterpret_cast<__nv_bfloat162*>(Col)[o1 >> 1] = l1;
            }
        }
    }
}

// ---------------- split (same layout): fp32 -> bf16 hi/lo ----------------
template<bool RELU>
__global__ void split_rm(const float* __restrict__ in,
                         __nv_bfloat16* __restrict__ oh, __nv_bfloat16* __restrict__ ol,
                         long long n, long long zin, long long zout)
{
    long long i = ((long long)blockIdx.x * blockDim.x + threadIdx.x) * 4;
    if (i >= n) return;
    float4 v = *reinterpret_cast<const float4*>(in + (long long)blockIdx.y * zin + i);
    if (RELU) {
        v.x = fmaxf(v.x, 0.f); v.y = fmaxf(v.y, 0.f);
        v.z = fmaxf(v.z, 0.f); v.w = fmaxf(v.w, 0.f);
    }
    __nv_bfloat162 h0 = __floats2bfloat162_rn(v.x, v.y);
    __nv_bfloat162 h1 = __floats2bfloat162_rn(v.z, v.w);
    __nv_bfloat162 l0 = __floats2bfloat162_rn(v.x - __bfloat162float(h0.x), v.y - __bfloat162float(h0.y));
    __nv_bfloat162 l1 = __floats2bfloat162_rn(v.z - __bfloat162float(h1.x), v.w - __bfloat162float(h1.y));
    uint2 hv = make_uint2(pack2(h0), pack2(h1));
    uint2 lv = make_uint2(pack2(l0), pack2(l1));
    *reinterpret_cast<uint2*>(oh + (long long)blockIdx.y * zout + i) = hv;
    *reinterpret_cast<uint2*>(ol + (long long)blockIdx.y * zout + i) = lv;
}

// ---------------- transpose + split: fp32 (R,C) -> bf16 hi/lo (C,R) ----------------
template<bool RELU>
__global__ void transpose_split(const float* __restrict__ in,
                                __nv_bfloat16* __restrict__ oh, __nv_bfloat16* __restrict__ ol,
                                int R, int C, long long zin, long long zout)
{
    __shared__ float tile[32][33];
    const int tx = threadIdx.x, ty = threadIdx.y;
    const int r0 = blockIdx.y * 32, c0 = blockIdx.x * 32;
    const float* ip = in + (long long)blockIdx.z * zin;
#pragma unroll
    for (int i = 0; i < 4; ++i)
        tile[ty + 8 * i][tx] = ip[(long long)(r0 + ty + 8 * i) * C + c0 + tx];
    __syncthreads();
    const long long ob = (long long)blockIdx.z * zout;
#pragma unroll
    for (int i = 0; i < 4; ++i) {
        int c = c0 + ty + 8 * i, r = r0 + tx;
        float v = tile[tx][ty + 8 * i];
        if (RELU) v = fmaxf(v, 0.f);
        __nv_bfloat16 h = __float2bfloat16(v);
        __nv_bfloat16 l = __float2bfloat16(v - __bfloat162float(h));
        oh[ob + (long long)c * R + r] = h;
        ol[ob + (long long)c * R + r] = l;
    }
}

// ---------------- fused residual add + layernorm over last axis (1024) ----------------
__global__ void add_ln_kernel(const float* __restrict__ a, const float* __restrict__ b,
                              const float* __restrict__ w, const float* __restrict__ bias,
                              float* __restrict__ out)
{
    const int row = blockIdx.x;
    const int tid = threadIdx.x;
    const long long base = (long long)row * SEQ_;
    float v[4];
    float s = 0.f, ss = 0.f;
#pragma unroll
    for (int i = 0; i < 4; ++i) {
        int col = tid + i * 256;
        float t = a[base + col] + b[base + col];
        v[i] = t; s += t; ss += t * t;
    }
#pragma unroll
    for (int o = 16; o > 0; o >>= 1) {
        s  += __shfl_xor_sync(0xffffffffu, s,  o);
        ss += __shfl_xor_sync(0xffffffffu, ss, o);
    }
    __shared__ float rs[8], rss[8];
    if ((tid & 31) == 0) { rs[tid >> 5] = s; rss[tid >> 5] = ss; }
    __syncthreads();
    s = 0.f; ss = 0.f;
#pragma unroll
    for (int i = 0; i < 8; ++i) { s += rs[i]; ss += rss[i]; }
    const float mu  = s  * (1.0f / SEQ_);
    const float var = ss * (1.0f / SEQ_) - mu * mu;
    const float inv = rsqrtf(var + 1e-6f);
#pragma unroll
    for (int i = 0; i < 4; ++i) {
        int col = tid + i * 256;
        out[base + col] = (v[i] - mu) * inv * w[col] + bias[col];
    }
}

// ---------------- host orchestration ----------------
struct Bufs {
    float *sq, *att, *z1, *mout, *x1, *x2, *t;
    __nv_bfloat16 *wqh, *wql, *xTh, *xTl, *qh, *ql, *W1h, *W1l, *W2h, *W2l,
                  *hbh, *hbl, *qTh, *qTl, *kTh, *kTl, *vh, *vl, *bTh, *bTl,
                  *aTh, *aTl, *zTh, *zTl, *c1h, *c1l, *c2h, *c2l,
                  *Wah, *Wal, *Wbh, *Wbl;
};

static inline unsigned nb4(long long n) { return (unsigned)((n / 4 + 255) / 256); }

static void launch_mha(const float* x, const float* wqkv, const float* W1, const float* W2,
                       const float* cW1, const float* cW2, const Bufs& B)
{
    const float* nf = nullptr;
    __nv_bfloat16* nb = nullptr;

    // operand prep (splits + transposes)
    transpose_split<false><<<dim3(SEQ_/32, IN_/32, 1), dim3(32,8)>>>(x, B.xTh, B.xTl, IN_, SEQ_, 0, 0);
    split_rm<false><<<nb4(3LL*IN_*IN_), 256>>>(wqkv, B.wqh, B.wql, 3LL*IN_*IN_, 0, 0);
    split_rm<false><<<nb4(24LL*MID_*SEQ_), 256>>>(W1, B.W1h, B.W1l, 24LL*MID_*SEQ_, 0, 0);
    split_rm<false><<<nb4(24LL*SEQ_*MID_), 256>>>(W2, B.W2h, B.W2l, 24LL*SEQ_*MID_, 0, 0);
    split_rm<false><<<nb4((long long)MID_*H_*IN_), 256>>>(cW1, B.c1h, B.c1l, (long long)MID_*H_*IN_, 0, 0);
    split_rm<false><<<nb4((long long)IN_*MID_), 256>>>(cW2, B.c2h, B.c2l, (long long)IN_*MID_, 0, 0);

    // 1. qkvS = split(relu(wqkv[c] @ x))           M=IN N=SEQ K=IN, z=3
    gemm_hmma<true,false,1><<<dim3(SEQ_/BN, IN_/BM, 3), 256, GSMEM>>>(
        B.wqh, B.wql, B.xTh, B.xTl, nullptr, B.qh, B.ql, nf,
        IN_, SEQ_, IN_,
        (long long)IN_*IN_, 0,  0, 0,  (long long)IN_*SEQ_, 0,  1);

    // 2. hbS = split(relu(qkvS[c] @ W1[h,c]^T))    M=IN N=MID K=SEQ, z=24
    gemm_hmma<true,false,1><<<dim3(MID_/BN, IN_/BM, H_*3), 256, GSMEM>>>(
        B.qh, B.ql, B.W1h, B.W1l, nullptr, B.hbh, B.hbl, nf,
        IN_, MID_, SEQ_,
        0, (long long)IN_*SEQ_,
        (long long)3*MID_*SEQ_, (long long)MID_*SEQ_,
        (long long)3*IN_*MID_,  (long long)IN_*MID_, 3);

    // 3. sq = hbS @ W2^T (fp32)                    M=IN N=SEQ K=MID, z=24
    gemm_hmma<false,false,0><<<dim3(SEQ_/BN, IN_/BM, H_*3), 256, GSMEM>>>(
        B.hbh, B.hbl, B.W2h, B.W2l, B.sq, nb, nb, nf,
        IN_, SEQ_, MID_,
        (long long)3*IN_*MID_,  (long long)IN_*MID_,
        (long long)3*SEQ_*MID_, (long long)SEQ_*MID_,
        (long long)3*IN_*SEQ_,  (long long)IN_*SEQ_, 3);

    // q,k transposed+split; v split
    transpose_split<false><<<dim3(SEQ_/32, IN_/32, H_), dim3(32,8)>>>(
        B.sq, B.qTh, B.qTl, IN_, SEQ_, (long long)3*IN_*SEQ_, (long long)SEQ_*IN_);
    transpose_split<false><<<dim3(SEQ_/32, IN_/32, H_), dim3(32,8)>>>(
        B.sq + (long long)IN_*SEQ_, B.kTh, B.kTl, IN_, SEQ_, (long long)3*IN_*SEQ_, (long long)SEQ_*IN_);
    split_rm<false><<<dim3(nb4((long long)IN_*SEQ_), H_), 256>>>(
        B.sq + (long long)2*IN_*SEQ_, B.vh, B.vl, (long long)IN_*SEQ_,
        (long long)3*IN_*SEQ_, (long long)IN_*SEQ_);

    // 4. bTS = split(qT @ kT^T)                    M=SEQ N=SEQ K=IN, z=8
    gemm_hmma<false,false,1><<<dim3(SEQ_/BN, SEQ_/BM, H_), 256, GSMEM>>>(
        B.qTh, B.qTl, B.kTh, B.kTl, nullptr, B.bTh, B.bTl, nf,
        SEQ_, SEQ_, IN_,
        (long long)SEQ_*IN_, 0, (long long)SEQ_*IN_, 0, (long long)SEQ_*SEQ_, 0, 1);

    // 5. att = vS @ bTS^T (fp32)                   M=IN N=SEQ K=SEQ, z=8
    gemm_hmma<false,false,0><<<dim3(SEQ_/BN, IN_/BM, H_), 256, GSMEM>>>(
        B.vh, B.vl, B.bTh, B.bTl, B.att, nb, nb, nf,
        IN_, SEQ_, SEQ_,
        (long long)IN_*SEQ_, 0, (long long)SEQ_*SEQ_, 0, (long long)IN_*SEQ_, 0, 1);

    // attT (relu) for the concat-MLP
    transpose_split<true><<<dim3(SEQ_/32, (H_*IN_)/32, 1), dim3(32,8)>>>(
        B.att, B.aTh, B.aTl, H_*IN_, SEQ_, 0, 0);

    // 6. z1 = relu(cW1 @ relu(cat)) (fp32)         M=MID N=SEQ K=4096
    gemm_hmma<true,false,0><<<dim3(SEQ_/BN, MID_/BM, 1), 256, GSMEM>>>(
        B.c1h, B.c1l, B.aTh, B.aTl, B.z1, nb, nb, nf,
        MID_, SEQ_, H_*IN_, 0,0, 0,0, 0,0, 1);

    transpose_split<true><<<dim3(SEQ_/32, MID_/32, 1), dim3(32,8)>>>(
        B.z1, B.zTh, B.zTl, MID_, SEQ_, 0, 0);

    // 7. mout = cW2 @ relu(z1) (fp32)              M=IN N=SEQ K=MID
    gemm_hmma<false,false,0><<<dim3(SEQ_/BN, IN_/BM, 1), 256, GSMEM>>>(
        B.c2h, B.c2l, B.zTh, B.zTl, B.mout, nb, nb, nf,
        IN_, SEQ_, MID_, 0,0, 0,0, 0,0, 1);
}

static void launch_ffn(const float* x2, const float* Wa, const float* Wb,
                       float* tbuf, float* out, const Bufs& B)
{
    const float* nf = nullptr;
    __nv_bfloat16* nb = nullptr;
    split_rm<false><<<nb4((long long)MID_*IN_), 256>>>(Wa, B.Wah, B.Wal, (long long)MID_*IN_, 0, 0);
    split_rm<false><<<nb4((long long)IN_*MID_), 256>>>(Wb, B.Wbh, B.Wbl, (long long)IN_*MID_, 0, 0);

    // t = relu(Wa @ relu(x2))                      M=MID N=SEQ K=IN (x2T pre-split, relu'd)
    gemm_hmma<true,false,0><<<dim3(SEQ_/BN, MID_/BM, 1), 256, GSMEM>>>(
        B.Wah, B.Wal, B.xTh, B.xTl, tbuf, nb, nb, nf,
        MID_, SEQ_, IN_, 0,0, 0,0, 0,0, 1);
    transpose_split<true><<<dim3(SEQ_/32, MID_/32, 1), dim3(32,8)>>>(
        tbuf, B.zTh, B.zTl, MID_, SEQ_, 0, 0);
    // out = Wb @ relu(t) + x2                      M=IN N=SEQ K=MID
    gemm_hmma<false,true,0><<<dim3(SEQ_/BN, IN_/BM, 1), 256, GSMEM>>>(
        B.Wbh, B.Wbl, B.zTh, B.zTl, out, nb, nb, x2,
        IN_, SEQ_, MID_, 0,0, 0,0, 0,0, 1);
}

extern "C" void kernel_launch(void* const* d_in, const int* in_sizes, int n_in,
                              void* d_out, int out_size)
{
    (void)in_sizes; (void)n_in; (void)out_size;

    const float* inp     = (const float*)d_in[0];
    const float* w_qkv_1 = (const float*)d_in[1];
    const float* w_qkv_2 = (const float*)d_in[2];
    const float* mh1_W1  = (const float*)d_in[3];
    const float* mh1_W2  = (const float*)d_in[4];
    const float* mh2_W1  = (const float*)d_in[5];
    const float* mh2_W2  = (const float*)d_in[6];
    const float* c1_W1   = (const float*)d_in[7];
    const float* c1_W2   = (const float*)d_in[8];
    const float* c2_W1   = (const float*)d_in[9];
    const float* c2_W2   = (const float*)d_in[10];
    const float* l1_W1   = (const float*)d_in[11];
    const float* l1_W2   = (const float*)d_in[12];
    const float* l2_W1   = (const float*)d_in[13];
    const float* l2_W2   = (const float*)d_in[14];
    const float* norm_w  = (const float*)d_in[15];
    const float* norm_b  = (const float*)d_in[16];
    float* out = (float*)d_out;

    // opt-in dynamic smem for all gemm instantiations
    cudaFuncSetAttribute(gemm_hmma<true,false,1>,  cudaFuncAttributeMaxDynamicSharedMemorySize, GSMEM);
    cudaFuncSetAttribute(gemm_hmma<false,false,1>, cudaFuncAttributeMaxDynamicSharedMemorySize, GSMEM);
    cudaFuncSetAttribute(gemm_hmma<false,false,0>, cudaFuncAttributeMaxDynamicSharedMemorySize, GSMEM);
    cudaFuncSetAttribute(gemm_hmma<true,false,0>,  cudaFuncAttributeMaxDynamicSharedMemorySize, GSMEM);
    cudaFuncSetAttribute(gemm_hmma<false,true,0>,  cudaFuncAttributeMaxDynamicSharedMemorySize, GSMEM);

    Bufs B;
    cudaGetSymbolAddress((void**)&B.sq,   g_sq);
    cudaGetSymbolAddress((void**)&B.att,  g_att);
    cudaGetSymbolAddress((void**)&B.z1,   g_z1);
    cudaGetSymbolAddress((void**)&B.mout, g_mout);
    cudaGetSymbolAddress((void**)&B.x1,   g_x1);
    cudaGetSymbolAddress((void**)&B.x2,   g_x2);
    cudaGetSymbolAddress((void**)&B.t,    g_t);
    cudaGetSymbolAddress((void**)&B.wqh,  g_wqS_h);  cudaGetSymbolAddress((void**)&B.wql, g_wqS_l);
    cudaGetSymbolAddress((void**)&B.xTh,  g_xT_h);   cudaGetSymbolAddress((void**)&B.xTl, g_xT_l);
    cudaGetSymbolAddress((void**)&B.qh,   g_qkvS_h); cudaGetSymbolAddress((void**)&B.ql,  g_qkvS_l);
    cudaGetSymbolAddress((void**)&B.W1h,  g_W1S_h);  cudaGetSymbolAddress((void**)&B.W1l, g_W1S_l);
    cudaGetSymbolAddress((void**)&B.W2h,  g_W2S_h);  cudaGetSymbolAddress((void**)&B.W2l, g_W2S_l);
    cudaGetSymbolAddress((void**)&B.hbh,  g_hbS_h);  cudaGetSymbolAddress((void**)&B.hbl, g_hbS_l);
    cudaGetSymbolAddress((void**)&B.qTh,  g_qT_h);   cudaGetSymbolAddress((void**)&B.qTl, g_qT_l);
    cudaGetSymbolAddress((void**)&B.kTh,  g_kT_h);   cudaGetSymbolAddress((void**)&B.kTl, g_kT_l);
    cudaGetSymbolAddress((void**)&B.vh,   g_vS_h);   cudaGetSymbolAddress((void**)&B.vl,  g_vS_l);
    cudaGetSymbolAddress((void**)&B.bTh,  g_bTS_h);  cudaGetSymbolAddress((void**)&B.bTl, g_bTS_l);
    cudaGetSymbolAddress((void**)&B.aTh,  g_aT_h);   cudaGetSymbolAddress((void**)&B.aTl, g_aT_l);
    cudaGetSymbolAddress((void**)&B.zTh,  g_zT_h);   cudaGetSymbolAddress((void**)&B.zTl, g_zT_l);
    cudaGetSymbolAddress((void**)&B.c1h,  g_cW1S_h); cudaGetSymbolAddress((void**)&B.c1l, g_cW1S_l);
    cudaGetSymbolAddress((void**)&B.c2h,  g_cW2S_h); cudaGetSymbolAddress((void**)&B.c2l, g_cW2S_l);
    cudaGetSymbolAddress((void**)&B.Wah,  g_WaS_h);  cudaGetSymbolAddress((void**)&B.Wal, g_WaS_l);
    cudaGetSymbolAddress((void**)&B.Wbh,  g_WbS_h);  cudaGetSymbolAddress((void**)&B.Wbl, g_WbS_l);

    // Block 1: x1 = LN(inp + MHA1(inp))
    launch_mha(inp, w_qkv_1, mh1_W1, mh1_W2, c1_W1, c1_W2, B);
    add_ln_kernel<<<IN_, 256>>>(inp, B.mout, norm_w, norm_b, B.x1);

    // Block 2: x2 = LN(inp + MHA2(x1))   (residual is inp, per reference)
    launch_mha(B.x1, w_qkv_2, mh2_W1, mh2_W2, c2_W1, c2_W2, B);
    add_ln_kernel<<<IN_, 256>>>(inp, B.mout, norm_w, norm_b, B.x2);

    // x2T (relu'd) shared by both FFN heads
    transpose_split<true><<<dim3(SEQ_/32, IN_/32, 1), dim3(32,8)>>>(
        B.x2, B.xTh, B.xTl, IN_, SEQ_, 0, 0);
    launch_ffn(B.x2, l1_W1, l1_W2, B.t, out, B);
    launch_ffn(B.x2, l2_W1, l2_W2, B.t, out + (long long)IN_ * SEQ_, B);
}

// round 13
// speedup vs baseline: 3.7276x; 1.0158x over previous
#include <cuda_runtime.h>
#include <cuda_bf16.h>
#include <cstdint>

// Problem dims
#define H_   8
#define IN_  512
#define SEQ_ 1024
#define MID_ 2048

// ---------------- HMMA GEMM tile config ----------------
constexpr int BM = 128, BN = 128, BK = 32;     // BK in bf16 k-elements per stage
constexpr int RSB = 80;                        // smem row stride bytes (64 data + 16 pad)
constexpr int OPB = 128 * RSB;                 // bytes per operand-half tile (10240)
constexpr int OFF_AHI = 0, OFF_ALO = OPB, OFF_BHI = 2 * OPB, OFF_BLO = 3 * OPB;
constexpr int STAGE = 4 * OPB;                 // 40960
constexpr int GSMEM = 2 * STAGE;               // 81920 bytes dynamic smem (also covers OM=2 transpose: 128*132*4=67584)

// ---------------- scratch (device globals; no allocation allowed) ----------------
__device__ float g_mout[IN_ * SEQ_];
__device__ float g_x1  [IN_ * SEQ_];
__device__ float g_x2  [IN_ * SEQ_];
// activation split buffers (reused sequentially)
__device__ __nv_bfloat16 g_xT_h  [SEQ_ * IN_],           g_xT_l  [SEQ_ * IN_];
__device__ __nv_bfloat16 g_qkvS_h[3 * IN_ * SEQ_],       g_qkvS_l[3 * IN_ * SEQ_];
__device__ __nv_bfloat16 g_hbS_h [H_ * 3 * IN_ * MID_],  g_hbS_l [H_ * 3 * IN_ * MID_];
__device__ __nv_bfloat16 g_qkT_h [2 * H_ * SEQ_ * IN_],  g_qkT_l [2 * H_ * SEQ_ * IN_];
__device__ __nv_bfloat16 g_vS_h  [H_ * IN_ * SEQ_],      g_vS_l  [H_ * IN_ * SEQ_];
__device__ __nv_bfloat16 g_bTS_h [H_ * SEQ_ * SEQ_],     g_bTS_l [H_ * SEQ_ * SEQ_];
__device__ __nv_bfloat16 g_aT_h  [SEQ_ * H_ * IN_],      g_aT_l  [SEQ_ * H_ * IN_];
__device__ __nv_bfloat16 g_zT_h  [SEQ_ * MID_],          g_zT_l  [SEQ_ * MID_];
// per-block weight splits (so block-2 splits overlap block-1 GEMMs)
__device__ __nv_bfloat16 g_wq1_h [3 * IN_ * IN_],        g_wq1_l [3 * IN_ * IN_];
__device__ __nv_bfloat16 g_wq2_h [3 * IN_ * IN_],        g_wq2_l [3 * IN_ * IN_];
__device__ __nv_bfloat16 g_W1a_h [H_ * 3 * MID_ * SEQ_], g_W1a_l [H_ * 3 * MID_ * SEQ_];
__device__ __nv_bfloat16 g_W1b_h [H_ * 3 * MID_ * SEQ_], g_W1b_l [H_ * 3 * MID_ * SEQ_];
__device__ __nv_bfloat16 g_W2a_h [H_ * 3 * SEQ_ * MID_], g_W2a_l [H_ * 3 * SEQ_ * MID_];
__device__ __nv_bfloat16 g_W2b_h [H_ * 3 * SEQ_ * MID_], g_W2b_l [H_ * 3 * SEQ_ * MID_];
__device__ __nv_bfloat16 g_c1a_h [MID_ * H_ * IN_],      g_c1a_l [MID_ * H_ * IN_];
__device__ __nv_bfloat16 g_c1b_h [MID_ * H_ * IN_],      g_c1b_l [MID_ * H_ * IN_];
__device__ __nv_bfloat16 g_c2a_h [IN_ * MID_],           g_c2a_l [IN_ * MID_];
__device__ __nv_bfloat16 g_c2b_h [IN_ * MID_],           g_c2b_l [IN_ * MID_];
__device__ __nv_bfloat16 g_Wa1_h [MID_ * IN_],           g_Wa1_l [MID_ * IN_];
__device__ __nv_bfloat16 g_Wb1_h [IN_ * MID_],           g_Wb1_l [IN_ * MID_];
__device__ __nv_bfloat16 g_Wa2_h [MID_ * IN_],           g_Wa2_l [MID_ * IN_];
__device__ __nv_bfloat16 g_Wb2_h [IN_ * MID_],           g_Wb2_l [IN_ * MID_];

// ---------------- PTX helpers ----------------
__device__ __forceinline__ uint32_t smem_u32(const void* p) {
    uint32_t a;
    asm("{ .reg .u64 t; cvta.to.shared.u64 t, %1; cvt.u32.u64 %0, t; }" : "=r"(a) : "l"(p));
    return a;
}
__device__ __forceinline__ void cpa16(uint32_t d, const void* s) {
    asm volatile("cp.async.cg.shared.global [%0], [%1], 16;" :: "r"(d), "l"(s));
}
__device__ __forceinline__ void cp_commit() {
    asm volatile("cp.async.commit_group;" ::: "memory");
}
template<int N> __device__ __forceinline__ void cp_wait() {
    asm volatile("cp.async.wait_group %0;" :: "n"(N) : "memory");
}
__device__ __forceinline__ void ldsm4(uint32_t& r0, uint32_t& r1, uint32_t& r2, uint32_t& r3, uint32_t a) {
    asm volatile("ldmatrix.sync.aligned.m8n8.x4.shared.b16 {%0,%1,%2,%3}, [%4];"
                 : "=r"(r0), "=r"(r1), "=r"(r2), "=r"(r3) : "r"(a));
}
__device__ __forceinline__ void mma_bf16(float c[4], const uint32_t a[4], const uint32_t b[2]) {
    asm volatile(
        "mma.sync.aligned.m16n8k16.row.col.f32.bf16.bf16.f32 "
        "{%0,%1,%2,%3}, {%4,%5,%6,%7}, {%8,%9}, {%0,%1,%2,%3};\n"
        : "+f"(c[0]), "+f"(c[1]), "+f"(c[2]), "+f"(c[3])
        : "r"(a[0]), "r"(a[1]), "r"(a[2]), "r"(a[3]), "r"(b[0]), "r"(b[1]));
}
__device__ __forceinline__ uint32_t pack2(__nv_bfloat162 h) {
    return *reinterpret_cast<uint32_t*>(&h);
}

// ---------------- GEMM: C = act( A * B^T [+Res] ), operands pre-split bf16 hi/lo ----------------
// A (M,K) row-major; B (N,K) row-major. 3-pass split: hi*hi + hi*lo + lo*hi, fp32 acc.
// OM=0: fp32 out (RO relu, RES residual). OM=1: bf16 hi/lo split out, same layout.
// OM=2: bf16 hi/lo split out TRANSPOSED (C^T row n = output row, ld = ldt; RO relu).
// z -> (z/zdiv)*s?1 + (z%zdiv)*s?2 batch offsets.
template<bool RO, bool RES, int OM>
__global__ void __launch_bounds__(256, 2)
gemm_hmma(const __nv_bfloat16* __restrict__ Ah, const __nv_bfloat16* __restrict__ Al,
          const __nv_bfloat16* __restrict__ Bh, const __nv_bfloat16* __restrict__ Bl,
          float* __restrict__ Cf, __nv_bfloat16* __restrict__ Coh, __nv_bfloat16* __restrict__ Col,
          const float* __restrict__ Res,
          int M, int N, int K, int ldt,
          long long sA1, long long sA2, long long sB1, long long sB2,
          long long sC1, long long sC2, int zdiv)
{
    extern __shared__ char smem[];
    const int tid = threadIdx.x, lane = tid & 31, warp = tid >> 5;

    const int zz = blockIdx.z, zh = zz / zdiv, zc = zz - zh * zdiv;
    const long long offA = zh * sA1 + (long long)zc * sA2;
    const long long offB = zh * sB1 + (long long)zc * sB2;
    const long long cOff = zh * sC1 + (long long)zc * sC2;

    const int bm = blockIdx.y * BM, bn = blockIdx.x * BN;
    const uint32_t sb = smem_u32(smem);

    const int srow = tid >> 2, skq = tid & 3;
    const __nv_bfloat16* pAh = Ah + offA + (long long)(bm + srow) * K + skq * 8;
    const __nv_bfloat16* pAl = Al + offA + (long long)(bm + srow) * K + skq * 8;
    const __nv_bfloat16* pBh = Bh + offB + (long long)(bn + srow) * K + skq * 8;
    const __nv_bfloat16* pBl = Bl + offB + (long long)(bn + srow) * K + skq * 8;
    const long long rstep = 64LL * K;
    const uint32_t sdst = srow * RSB + skq * 16;

    auto stage_load = [&](int t) {
        const int k0 = t * BK;
        const uint32_t d = sb + (t & 1) * STAGE + sdst;
        cpa16(d + OFF_AHI,            pAh + k0);
        cpa16(d + OFF_AHI + 64 * RSB, pAh + k0 + rstep);
        cpa16(d + OFF_ALO,            pAl + k0);
        cpa16(d + OFF_ALO + 64 * RSB, pAl + k0 + rstep);
        cpa16(d + OFF_BHI,            pBh + k0);
        cpa16(d + OFF_BHI + 64 * RSB, pBh + k0 + rstep);
        cpa16(d + OFF_BLO,            pBl + k0);
        cpa16(d + OFF_BLO + 64 * RSB, pBl + k0 + rstep);
        cp_commit();
    };

    float acc[4][4][4];
#pragma unroll
    for (int i = 0; i < 4; ++i)
#pragma unroll
        for (int j = 0; j < 4; ++j)
#pragma unroll
            for (int r = 0; r < 4; ++r) acc[i][j][r] = 0.f;

    const int wm = (warp & 1) * 64, wn = (warp >> 1) * 32;
    const int aRow   = wm + (lane & 7) + ((lane >> 3) & 1) * 8;
    const int aChunk = (lane >> 4) * 16;
    const int bRow   = wn + (lane & 7) + (lane >> 4) * 8;
    const int bChunk = ((lane >> 3) & 1) * 16;

    stage_load(0);
    const int nk = K / BK;

    for (int t = 0; t < nk; ++t) {
        if (t + 1 < nk) { stage_load(t + 1); cp_wait<1>(); }
        else            { cp_wait<0>(); }
        __syncthreads();

        const uint32_t ss = sb + (t & 1) * STAGE;
#pragma unroll
        for (int kk = 0; kk < 2; ++kk) {
            const uint32_t kb = kk * 32;
            uint32_t ah[4][4], bh2[4][2], bl2[4][2];
#pragma unroll
            for (int i = 0; i < 4; ++i)
                ldsm4(ah[i][0], ah[i][1], ah[i][2], ah[i][3],
                      ss + OFF_AHI + (aRow + i * 16) * RSB + kb + aChunk);
#pragma unroll
            for (int jj = 0; jj < 2; ++jj) {
                uint32_t r0, r1, r2, r3;
                ldsm4(r0, r1, r2, r3, ss + OFF_BHI + (bRow + jj * 16) * RSB + kb + bChunk);
                bh2[2 * jj][0] = r0; bh2[2 * jj][1] = r1;
                bh2[2 * jj + 1][0] = r2; bh2[2 * jj + 1][1] = r3;
            }
#pragma unroll
            for (int i = 0; i < 4; ++i)
#pragma unroll
                for (int j = 0; j < 4; ++j) mma_bf16(acc[i][j], ah[i], bh2[j]);
#pragma unroll
            for (int jj = 0; jj < 2; ++jj) {
                uint32_t r0, r1, r2, r3;
                ldsm4(r0, r1, r2, r3, ss + OFF_BLO + (bRow + jj * 16) * RSB + kb + bChunk);
                bl2[2 * jj][0] = r0; bl2[2 * jj][1] = r1;
                bl2[2 * jj + 1][0] = r2; bl2[2 * jj + 1][1] = r3;
            }
#pragma unroll
            for (int i = 0; i < 4; ++i)
#pragma unroll
                for (int j = 0; j < 4; ++j) mma_bf16(acc[i][j], ah[i], bl2[j]);
#pragma unroll
            for (int i = 0; i < 4; ++i)
                ldsm4(ah[i][0], ah[i][1], ah[i][2], ah[i][3],
                      ss + OFF_ALO + (aRow + i * 16) * RSB + kb + aChunk);
#pragma unroll
            for (int i = 0; i < 4; ++i)
#pragma unroll
                for (int j = 0; j < 4; ++j) mma_bf16(acc[i][j], ah[i], bh2[j]);
        }
        __syncthreads();
    }

    const int ar = lane >> 2, ac = lane & 3;

    if (OM == 2) {
        // smem transpose -> coalesced transposed-split store. Store banks:
        // (132*n + m) mod 32 = (4n+m) mod 32 = (8ac+ar+const) -> bijection, conflict-free.
        float* tb = reinterpret_cast<float*>(smem);
        const int TLD = 132;
#pragma unroll
        for (int i = 0; i < 4; ++i) {
            int m0 = wm + i * 16 + ar;
#pragma unroll
            for (int j = 0; j < 4; ++j) {
                int n0 = wn + j * 8 + ac * 2;
                float v0 = acc[i][j][0], v1 = acc[i][j][1];
                float v2 = acc[i][j][2], v3 = acc[i][j][3];
                if (RO) {
                    v0 = fmaxf(v0, 0.f); v1 = fmaxf(v1, 0.f);
                    v2 = fmaxf(v2, 0.f); v3 = fmaxf(v3, 0.f);
                }
                tb[n0 * TLD + m0]           = v0;
                tb[(n0 + 1) * TLD + m0]     = v1;
                tb[n0 * TLD + m0 + 8]       = v2;
                tb[(n0 + 1) * TLD + m0 + 8] = v3;
            }
        }
        __syncthreads();
        const int n = tid >> 1, mh = (tid & 1) * 64;
        const long long ro = cOff + (long long)(bn + n) * ldt + bm + mh;
#pragma unroll
        for (int mm = 0; mm < 64; mm += 8) {
            float4 a = *reinterpret_cast<float4*>(&tb[n * TLD + mh + mm]);
            float4 b = *reinterpret_cast<float4*>(&tb[n * TLD + mh + mm + 4]);
            __nv_bfloat162 h0 = __floats2bfloat162_rn(a.x, a.y), h1 = __floats2bfloat162_rn(a.z, a.w);
            __nv_bfloat162 h2 = __floats2bfloat162_rn(b.x, b.y), h3 = __floats2bfloat162_rn(b.z, b.w);
            __nv_bfloat162 l0 = __floats2bfloat162_rn(a.x - __bfloat162float(h0.x), a.y - __bfloat162float(h0.y));
            __nv_bfloat162 l1 = __floats2bfloat162_rn(a.z - __bfloat162float(h1.x), a.w - __bfloat162float(h1.y));
            __nv_bfloat162 l2 = __floats2bfloat162_rn(b.x - __bfloat162float(h2.x), b.y - __bfloat162float(h2.y));
            __nv_bfloat162 l3 = __floats2bfloat162_rn(b.z - __bfloat162float(h3.x), b.w - __bfloat162float(h3.y));
            *reinterpret_cast<uint4*>(Coh + ro + mm) = make_uint4(pack2(h0), pack2(h1), pack2(h2), pack2(h3));
            *reinterpret_cast<uint4*>(Col + ro + mm) = make_uint4(pack2(l0), pack2(l1), pack2(l2), pack2(l3));
        }
        return;
    }

#pragma unroll
    for (int i = 0; i < 4; ++i) {
        int m0 = bm + wm + i * 16 + ar;
#pragma unroll
        for (int j = 0; j < 4; ++j) {
            int n0 = bn + wn + j * 8 + ac * 2;
            long long o0 = cOff + (long long)m0 * N + n0;
            long long o1 = o0 + 8LL * N;
            float v0 = acc[i][j][0], v1 = acc[i][j][1];
            float v2 = acc[i][j][2], v3 = acc[i][j][3];
            if (RES) {
                v0 += Res[o0]; v1 += Res[o0 + 1];
                v2 += Res[o1]; v3 += Res[o1 + 1];
            }
            if (RO) {
                v0 = fmaxf(v0, 0.f); v1 = fmaxf(v1, 0.f);
                v2 = fmaxf(v2, 0.f); v3 = fmaxf(v3, 0.f);
            }
            if (OM == 0) {
                *reinterpret_cast<float2*>(Cf + o0) = make_float2(v0, v1);
                *reinterpret_cast<float2*>(Cf + o1) = make_float2(v2, v3);
            } else {
                __nv_bfloat162 h0 = __floats2bfloat162_rn(v0, v1);
                __nv_bfloat162 l0 = __floats2bfloat162_rn(v0 - __bfloat162float(h0.x),
                                                          v1 - __bfloat162float(h0.y));
                __nv_bfloat162 h1 = __floats2bfloat162_rn(v2, v3);
                __nv_bfloat162 l1 = __floats2bfloat162_rn(v2 - __bfloat162float(h1.x),
                                                          v3 - __bfloat162float(h1.y));
                reinterpret_cast<__nv_bfloat162*>(Coh)[o0 >> 1] = h0;
                reinterpret_cast<__nv_bfloat162*>(Col)[o0 >> 1] = l0;
                reinterpret_cast<__nv_bfloat162*>(Coh)[o1 >> 1] = h1;
                reinterpret_cast<__nv_bfloat162*>(Col)[o1 >> 1] = l1;
            }
        }
    }
}

// ---------------- split (same layout): fp32 -> bf16 hi/lo ----------------
__global__ void split_rm(const float* __restrict__ in,
                         __nv_bfloat16* __restrict__ oh, __nv_bfloat16* __restrict__ ol,
                         long long n)
{
    long long i = ((long long)blockIdx.x * blockDim.x + threadIdx.x) * 4;
    if (i >= n) return;
    float4 v = *reinterpret_cast<const float4*>(in + i);
    __nv_bfloat162 h0 = __floats2bfloat162_rn(v.x, v.y);
    __nv_bfloat162 h1 = __floats2bfloat162_rn(v.z, v.w);
    __nv_bfloat162 l0 = __floats2bfloat162_rn(v.x - __bfloat162float(h0.x), v.y - __bfloat162float(h0.y));
    __nv_bfloat162 l1 = __floats2bfloat162_rn(v.z - __bfloat162float(h1.x), v.w - __bfloat162float(h1.y));
    *reinterpret_cast<uint2*>(oh + i) = make_uint2(pack2(h0), pack2(h1));
    *reinterpret_cast<uint2*>(ol + i) = make_uint2(pack2(l0), pack2(l1));
}

// ---------------- transpose + split: fp32 (R,C) -> bf16 hi/lo (C,R) ----------------
template<bool RELU>
__global__ void transpose_split(const float* __restrict__ in,
                                __nv_bfloat16* __restrict__ oh, __nv_bfloat16* __restrict__ ol,
                                int R, int C)
{
    __shared__ float tile[32][33];
    const int tx = threadIdx.x, ty = threadIdx.y;
    const int r0 = blockIdx.y * 32, c0 = blockIdx.x * 32;
#pragma unroll
    for (int i = 0; i < 4; ++i)
        tile[ty + 8 * i][tx] = in[(long long)(r0 + ty + 8 * i) * C + c0 + tx];
    __syncthreads();
#pragma unroll
    for (int i = 0; i < 4; ++i) {
        int c = c0 + ty + 8 * i, r = r0 + tx;
        float v = tile[tx][ty + 8 * i];
        if (RELU) v = fmaxf(v, 0.f);
        __nv_bfloat16 h = __float2bfloat16(v);
        __nv_bfloat16 l = __float2bfloat16(v - __bfloat162float(h));
        oh[(long long)c * R + r] = h;
        ol[(long long)c * R + r] = l;
    }
}

// ---------------- fused residual add + layernorm over last axis (1024) ----------------
__global__ void add_ln_kernel(const float* __restrict__ a, const float* __restrict__ b,
                              const float* __restrict__ w, const float* __restrict__ bias,
                              float* __restrict__ out)
{
    const int row = blockIdx.x;
    const int tid = threadIdx.x;
    const long long base = (long long)row * SEQ_;
    float v[4];
    float s = 0.f, ss = 0.f;
#pragma unroll
    for (int i = 0; i < 4; ++i) {
        int col = tid + i * 256;
        float t = a[base + col] + b[base + col];
        v[i] = t; s += t; ss += t * t;
    }
#pragma unroll
    for (int o = 16; o > 0; o >>= 1) {
        s  += __shfl_xor_sync(0xffffffffu, s,  o);
        ss += __shfl_xor_sync(0xffffffffu, ss, o);
    }
    __shared__ float rs[8], rss[8];
    if ((tid & 31) == 0) { rs[tid >> 5] = s; rss[tid >> 5] = ss; }
    __syncthreads();
    s = 0.f; ss = 0.f;
#pragma unroll
    for (int i = 0; i < 8; ++i) { s += rs[i]; ss += rss[i]; }
    const float mu  = s  * (1.0f / SEQ_);
    const float var = ss * (1.0f / SEQ_) - mu * mu;
    const float inv = rsqrtf(var + 1e-6f);
#pragma unroll
    for (int i = 0; i < 4; ++i) {
        int col = tid + i * 256;
        out[base + col] = (v[i] - mu) * inv * w[col] + bias[col];
    }
}

// ---------------- host orchestration ----------------
struct WSet {  // one block's pre-split weights
    __nv_bfloat16 *wqh, *wql, *W1h, *W1l, *W2h, *W2l, *c1h, *c1l, *c2h, *c2l;
};
struct Bufs {
    float *mout, *x1, *x2;
    __nv_bfloat16 *xTh, *xTl, *qh, *ql, *hbh, *hbl, *qkTh, *qkTl,
                  *vh, *vl, *bTh, *bTl, *aTh, *aTl, *zTh, *zTl;
};

static inline unsigned nb4(long long n) { return (unsigned)((n / 4 + 255) / 256); }
static inline void wait_ev(cudaEvent_t ev) { cudaStreamWaitEvent((cudaStream_t)0, ev, 0); }

static void launch_mha(const WSet& W, const Bufs& B)
{
    const float* nf = nullptr;
    __nv_bfloat16* nb = nullptr;
    const long long IS = (long long)IN_ * SEQ_;
    const long long IM = (long long)IN_ * MID_;
    const long long SM = (long long)SEQ_ * MID_;
    const long long SI = (long long)SEQ_ * IN_;

    // 1. qkvS = split(relu(wqkv[c] @ x))           M=IN N=SEQ K=IN, z=3
    gemm_hmma<true,false,1><<<dim3(SEQ_/BN, IN_/BM, 3), 256, GSMEM>>>(
        W.wqh, W.wql, B.xTh, B.xTl, nullptr, B.qh, B.ql, nf,
        IN_, SEQ_, IN_, 0,
        (long long)IN_*IN_, 0,  0, 0,  IS, 0,  1);

    // 2. hbS = split(relu(qkvS[c] @ W1[h,c]^T))    M=IN N=MID K=SEQ, z=24
    gemm_hmma<true,false,1><<<dim3(MID_/BN, IN_/BM, H_*3), 256, GSMEM>>>(
        B.qh, B.ql, W.W1h, W.W1l, nullptr, B.hbh, B.hbl, nf,
        IN_, MID_, SEQ_, 0,
        0, IS,  3*MID_*(long long)SEQ_, (long long)MID_*SEQ_,  3*IM, IM, 3);

    // 3a. qkT = splitT(hbS[h,c] @ W2[h,c]^T), c in {q,k}   z=16, OM=2
    gemm_hmma<false,false,2><<<dim3(SEQ_/BN, IN_/BM, H_*2), 256, GSMEM>>>(
        B.hbh, B.hbl, W.W2h, W.W2l, nullptr, B.qkTh, B.qkTl, nf,
        IN_, SEQ_, MID_, IN_,
        3*IM, IM,  3*SM, SM,  SI, (long long)H_*SI, 2);

    // 3b. vS = split(hbS[h,2] @ W2[h,2]^T)                 z=8, OM=1
    gemm_hmma<false,false,1><<<dim3(SEQ_/BN, IN_/BM, H_), 256, GSMEM>>>(
        B.hbh + 2*IM, B.hbl + 2*IM, W.W2h + 2*SM, W.W2l + 2*SM, nullptr, B.vh, B.vl, nf,
        IN_, SEQ_, MID_, 0,
        3*IM, 0,  3*SM, 0,  IS, 0, 1);

    // 4. bTS = split(qT @ kT^T)                    M=SEQ N=SEQ K=IN, z=8
    gemm_hmma<false,false,1><<<dim3(SEQ_/BN, SEQ_/BM, H_), 256, GSMEM>>>(
        B.qkTh, B.qkTl, B.qkTh + (long long)H_*SI, B.qkTl + (long long)H_*SI,
        nullptr, B.bTh, B.bTl, nf,
        SEQ_, SEQ_, IN_, 0,
        SI, 0,  SI, 0,  (long long)SEQ_*SEQ_, 0, 1);

    // 5. aT = splitT(relu(vS @ bTS^T))             M=IN N=SEQ K=SEQ, z=8, OM=2
    gemm_hmma<true,false,2><<<dim3(SEQ_/BN, IN_/BM, H_), 256, GSMEM>>>(
        B.vh, B.vl, B.bTh, B.bTl, nullptr, B.aTh, B.aTl, nf,
        IN_, SEQ_, SEQ_, H_*IN_,
        IS, 0,  (long long)SEQ_*SEQ_, 0,  IN_, 0, 1);

    // 6. zT = splitT(relu(cW1 @ relu(cat)))        M=MID N=SEQ K=4096, OM=2
    gemm_hmma<true,false,2><<<dim3(SEQ_/BN, MID_/BM, 1), 256, GSMEM>>>(
        W.c1h, W.c1l, B.aTh, B.aTl, nullptr, B.zTh, B.zTl, nf,
        MID_, SEQ_, H_*IN_, MID_, 0,0, 0,0, 0,0, 1);

    // 7. mout = cW2 @ relu(z1) (fp32)              M=IN N=SEQ K=MID
    gemm_hmma<false,false,0><<<dim3(SEQ_/BN, IN_/BM, 1), 256, GSMEM>>>(
        W.c2h, W.c2l, B.zTh, B.zTl, B.mout, nb, nb, nf,
        IN_, SEQ_, MID_, 0, 0,0, 0,0, 0,0, 1);
}

static void launch_ffn(const float* x2, const __nv_bfloat16* Wah, const __nv_bfloat16* Wal,
                       const __nv_bfloat16* Wbh, const __nv_bfloat16* Wbl,
                       float* out, const Bufs& B)
{
    const float* nf = nullptr;
    __nv_bfloat16* nb = nullptr;
    // zT = splitT(relu(Wa @ relu(x2)))             M=MID N=SEQ K=IN, OM=2
    gemm_hmma<true,false,2><<<dim3(SEQ_/BN, MID_/BM, 1), 256, GSMEM>>>(
        Wah, Wal, B.xTh, B.xTl, nullptr, B.zTh, B.zTl, nf,
        MID_, SEQ_, IN_, MID_, 0,0, 0,0, 0,0, 1);
    // out = Wb @ relu(t) + x2                      M=IN N=SEQ K=MID
    gemm_hmma<false,true,0><<<dim3(SEQ_/BN, IN_/BM, 1), 256, GSMEM>>>(
        Wbh, Wbl, B.zTh, B.zTl, out, nb, nb, x2,
        IN_, SEQ_, MID_, 0, 0,0, 0,0, 0,0, 1);
}

extern "C" void kernel_launch(void* const* d_in, const int* in_sizes, int n_in,
                              void* d_out, int out_size)
{
    (void)in_sizes; (void)n_in; (void)out_size;

    const float* inp     = (const float*)d_in[0];
    const float* w_qkv_1 = (const float*)d_in[1];
    const float* w_qkv_2 = (const float*)d_in[2];
    const float* mh1_W1  = (const float*)d_in[3];
    const float* mh1_W2  = (const float*)d_in[4];
    const float* mh2_W1  = (const float*)d_in[5];
    const float* mh2_W2  = (const float*)d_in[6];
    const float* c1_W1   = (const float*)d_in[7];
    const float* c1_W2   = (const float*)d_in[8];
    const float* c2_W1   = (const float*)d_in[9];
    const float* c2_W2   = (const float*)d_in[10];
    const float* l1_W1   = (const float*)d_in[11];
    const float* l1_W2   = (const float*)d_in[12];
    const float* l2_W1   = (const float*)d_in[13];
    const float* l2_W2   = (const float*)d_in[14];
    const float* norm_w  = (const float*)d_in[15];
    const float* norm_b  = (const float*)d_in[16];
    float* out = (float*)d_out;

    static bool inited = false;
    static cudaStream_t s2;
    static cudaEvent_t evS, evA, evB, evC, evD, evE, evF;
    if (!inited) {
        cudaStreamCreateWithFlags(&s2, cudaStreamNonBlocking);
        cudaEventCreateWithFlags(&evS, cudaEventDisableTiming);
        cudaEventCreateWithFlags(&evA, cudaEventDisableTiming);
        cudaEventCreateWithFlags(&evB, cudaEventDisableTiming);
        cudaEventCreateWithFlags(&evC, cudaEventDisableTiming);
        cudaEventCreateWithFlags(&evD, cudaEventDisableTiming);
        cudaEventCreateWithFlags(&evE, cudaEventDisableTiming);
        cudaEventCreateWithFlags(&evF, cudaEventDisableTiming);
        cudaFuncSetAttribute(gemm_hmma<true,false,1>,  cudaFuncAttributeMaxDynamicSharedMemorySize, GSMEM);
        cudaFuncSetAttribute(gemm_hmma<false,false,1>, cudaFuncAttributeMaxDynamicSharedMemorySize, GSMEM);
        cudaFuncSetAttribute(gemm_hmma<false,false,2>, cudaFuncAttributeMaxDynamicSharedMemorySize, GSMEM);
        cudaFuncSetAttribute(gemm_hmma<true,false,2>,  cudaFuncAttributeMaxDynamicSharedMemorySize, GSMEM);
        cudaFuncSetAttribute(gemm_hmma<false,false,0>, cudaFuncAttributeMaxDynamicSharedMemorySize, GSMEM);
        cudaFuncSetAttribute(gemm_hmma<false,true,0>,  cudaFuncAttributeMaxDynamicSharedMemorySize, GSMEM);
        inited = true;
    }

    Bufs B;
    cudaGetSymbolAddress((void**)&B.mout, g_mout);
    cudaGetSymbolAddress((void**)&B.x1,   g_x1);
    cudaGetSymbolAddress((void**)&B.x2,   g_x2);
    cudaGetSymbolAddress((void**)&B.xTh,  g_xT_h);   cudaGetSymbolAddress((void**)&B.xTl,  g_xT_l);
    cudaGetSymbolAddress((void**)&B.qh,   g_qkvS_h); cudaGetSymbolAddress((void**)&B.ql,   g_qkvS_l);
    cudaGetSymbolAddress((void**)&B.hbh,  g_hbS_h);  cudaGetSymbolAddress((void**)&B.hbl,  g_hbS_l);
    cudaGetSymbolAddress((void**)&B.qkTh, g_qkT_h);  cudaGetSymbolAddress((void**)&B.qkTl, g_qkT_l);
    cudaGetSymbolAddress((void**)&B.vh,   g_vS_h);   cudaGetSymbolAddress((void**)&B.vl,   g_vS_l);
    cudaGetSymbolAddress((void**)&B.bTh,  g_bTS_h);  cudaGetSymbolAddress((void**)&B.bTl,  g_bTS_l);
    cudaGetSymbolAddress((void**)&B.aTh,  g_aT_h);   cudaGetSymbolAddress((void**)&B.aTl,  g_aT_l);
    cudaGetSymbolAddress((void**)&B.zTh,  g_zT_h);   cudaGetSymbolAddress((void**)&B.zTl,  g_zT_l);

    WSet W1s, W2s;
    cudaGetSymbolAddress((void**)&W1s.wqh, g_wq1_h); cudaGetSymbolAddress((void**)&W1s.wql, g_wq1_l);
    cudaGetSymbolAddress((void**)&W1s.W1h, g_W1a_h); cudaGetSymbolAddress((void**)&W1s.W1l, g_W1a_l);
    cudaGetSymbolAddress((void**)&W1s.W2h, g_W2a_h); cudaGetSymbolAddress((void**)&W1s.W2l, g_W2a_l);
    cudaGetSymbolAddress((void**)&W1s.c1h, g_c1a_h); cudaGetSymbolAddress((void**)&W1s.c1l, g_c1a_l);
    cudaGetSymbolAddress((void**)&W1s.c2h, g_c2a_h); cudaGetSymbolAddress((void**)&W1s.c2l, g_c2a_l);
    cudaGetSymbolAddress((void**)&W2s.wqh, g_wq2_h); cudaGetSymbolAddress((void**)&W2s.wql, g_wq2_l);
    cudaGetSymbolAddress((void**)&W2s.W1h, g_W1b_h); cudaGetSymbolAddress((void**)&W2s.W1l, g_W1b_l);
    cudaGetSymbolAddress((void**)&W2s.W2h, g_W2b_h); cudaGetSymbolAddress((void**)&W2s.W2l, g_W2b_l);
    cudaGetSymbolAddress((void**)&W2s.c1h, g_c1b_h); cudaGetSymbolAddress((void**)&W2s.c1l, g_c1b_l);
    cudaGetSymbolAddress((void**)&W2s.c2h, g_c2b_h); cudaGetSymbolAddress((void**)&W2s.c2l, g_c2b_l);
    __nv_bfloat16 *Wa1h, *Wa1l, *Wb1h, *Wb1l, *Wa2h, *Wa2l, *Wb2h, *Wb2l;
    cudaGetSymbolAddress((void**)&Wa1h, g_Wa1_h); cudaGetSymbolAddress((void**)&Wa1l, g_Wa1_l);
    cudaGetSymbolAddress((void**)&Wb1h, g_Wb1_h); cudaGetSymbolAddress((void**)&Wb1l, g_Wb1_l);
    cudaGetSymbolAddress((void**)&Wa2h, g_Wa2_h); cudaGetSymbolAddress((void**)&Wa2l, g_Wa2_l);
    cudaGetSymbolAddress((void**)&Wb2h, g_Wb2_h); cudaGetSymbolAddress((void**)&Wb2l, g_Wb2_l);

    const long long nWQ = 3LL*IN_*IN_, nW1 = 24LL*MID_*SEQ_, nW2 = 24LL*SEQ_*MID_;
    const long long nC1 = (long long)MID_*H_*IN_, nC2 = (long long)IN_*MID_;
    const long long nWa = (long long)MID_*IN_, nWb = (long long)IN_*MID_;

    // ---- fork side stream: all weight splits overlap the GEMM chain ----
    cudaEventRecord(evS, 0);
    cudaStreamWaitEvent(s2, evS, 0);
    split_rm<<<nb4(nWQ), 256, 0, s2>>>(w_qkv_1, W1s.wqh, W1s.wql, nWQ);
    cudaEventRecord(evA, s2);
    split_rm<<<nb4(nW1), 256, 0, s2>>>(mh1_W1, W1s.W1h, W1s.W1l, nW1);
    cudaEventRecord(evB, s2);
    split_rm<<<nb4(nW2), 256, 0, s2>>>(mh1_W2, W1s.W2h, W1s.W2l, nW2);
    cudaEventRecord(evC, s2);
    split_rm<<<nb4(nC1), 256, 0, s2>>>(c1_W1, W1s.c1h, W1s.c1l, nC1);
    split_rm<<<nb4(nC2), 256, 0, s2>>>(c1_W2, W1s.c2h, W1s.c2l, nC2);
    cudaEventRecord(evD, s2);
    split_rm<<<nb4(nWQ), 256, 0, s2>>>(w_qkv_2, W2s.wqh, W2s.wql, nWQ);
    split_rm<<<nb4(nW1), 256, 0, s2>>>(mh2_W1, W2s.W1h, W2s.W1l, nW1);
    split_rm<<<nb4(nW2), 256, 0, s2>>>(mh2_W2, W2s.W2h, W2s.W2l, nW2);
    split_rm<<<nb4(nC1), 256, 0, s2>>>(c2_W1, W2s.c1h, W2s.c1l, nC1);
    split_rm<<<nb4(nC2), 256, 0, s2>>>(c2_W2, W2s.c2h, W2s.c2l, nC2);
    cudaEventRecord(evE, s2);
    split_rm<<<nb4(nWa), 256, 0, s2>>>(l1_W1, Wa1h, Wa1l, nWa);
    split_rm<<<nb4(nWb), 256, 0, s2>>>(l1_W2, Wb1h, Wb1l, nWb);
    split_rm<<<nb4(nWa), 256, 0, s2>>>(l2_W1, Wa2h, Wa2l, nWa);
    split_rm<<<nb4(nWb), 256, 0, s2>>>(l2_W2, Wb2h, Wb2l, nWb);
    cudaEventRecord(evF, s2);

    // ---- main chain ----
    // Block 1: x1 = LN(inp + MHA1(inp))
    transpose_split<false><<<dim3(SEQ_/32, IN_/32), dim3(32,8)>>>(inp, B.xTh, B.xTl, IN_, SEQ_);
    wait_ev(evA);
    // fine-grained waits inside: GEMM1 needs wq (evA); GEMM2 needs W1 (evB); GEMM3 needs W2 (evC); GEMM6 needs cW (evD)
    {
        // GEMM1
        gemm_hmma<true,false,1><<<dim3(SEQ_/BN, IN_/BM, 3), 256, GSMEM>>>(
            W1s.wqh, W1s.wql, B.xTh, B.xTl, nullptr, B.qh, B.ql, nullptr,
            IN_, SEQ_, IN_, 0, (long long)IN_*IN_, 0, 0, 0, (long long)IN_*SEQ_, 0, 1);
        wait_ev(evB);
        gemm_hmma<true,false,1><<<dim3(MID_/BN, IN_/BM, H_*3), 256, GSMEM>>>(
            B.qh, B.ql, W1s.W1h, W1s.W1l, nullptr, B.hbh, B.hbl, nullptr,
            IN_, MID_, SEQ_, 0, 0, (long long)IN_*SEQ_,
            3LL*MID_*SEQ_, (long long)MID_*SEQ_, 3LL*IN_*MID_, (long long)IN_*MID_, 3);
        wait_ev(evC);
        const long long IM = (long long)IN_*MID_, SM = (long long)SEQ_*MID_,
                        SI = (long long)SEQ_*IN_, IS = (long long)IN_*SEQ_;
        gemm_hmma<false,false,2><<<dim3(SEQ_/BN, IN_/BM, H_*2), 256, GSMEM>>>(
            B.hbh, B.hbl, W1s.W2h, W1s.W2l, nullptr, B.qkTh, B.qkTl, nullptr,
            IN_, SEQ_, MID_, IN_, 3*IM, IM, 3*SM, SM, SI, (long long)H_*SI, 2);
        gemm_hmma<false,false,1><<<dim3(SEQ_/BN, IN_/BM, H_), 256, GSMEM>>>(
            B.hbh + 2*IM, B.hbl + 2*IM, W1s.W2h + 2*SM, W1s.W2l + 2*SM, nullptr, B.vh, B.vl, nullptr,
            IN_, SEQ_, MID_, 0, 3*IM, 0, 3*SM, 0, IS, 0, 1);
        gemm_hmma<false,false,1><<<dim3(SEQ_/BN, SEQ_/BM, H_), 256, GSMEM>>>(
            B.qkTh, B.qkTl, B.qkTh + (long long)H_*SI, B.qkTl + (long long)H_*SI,
            nullptr, B.bTh, B.bTl, nullptr,
            SEQ_, SEQ_, IN_, 0, SI, 0, SI, 0, (long long)SEQ_*SEQ_, 0, 1);
        gemm_hmma<true,false,2><<<dim3(SEQ_/BN, IN_/BM, H_), 256, GSMEM>>>(
            B.vh, B.vl, B.bTh, B.bTl, nullptr, B.aTh, B.aTl, nullptr,
            IN_, SEQ_, SEQ_, H_*IN_, IS, 0, (long long)SEQ_*SEQ_, 0, IN_, 0, 1);
        wait_ev(evD);
        gemm_hmma<true,false,2><<<dim3(SEQ_/BN, MID_/BM, 1), 256, GSMEM>>>(
            W1s.c1h, W1s.c1l, B.aTh, B.aTl, nullptr, B.zTh, B.zTl, nullptr,
            MID_, SEQ_, H_*IN_, MID_, 0,0, 0,0, 0,0, 1);
        gemm_hmma<false,false,0><<<dim3(SEQ_/BN, IN_/BM, 1), 256, GSMEM>>>(
            W1s.c2h, W1s.c2l, B.zTh, B.zTl, B.mout, (__nv_bfloat16*)nullptr, (__nv_bfloat16*)nullptr, nullptr,
            IN_, SEQ_, MID_, 0, 0,0, 0,0, 0,0, 1);
    }
    add_ln_kernel<<<IN_, 256>>>(inp, B.mout, norm_w, norm_b, B.x1);

    // Block 2: x2 = LN(inp + MHA2(x1))  (residual is inp, per reference)
    transpose_split<false><<<dim3(SEQ_/32, IN_/32), dim3(32,8)>>>(B.x1, B.xTh, B.xTl, IN_, SEQ_);
    wait_ev(evE);
    launch_mha(W2s, B);
    add_ln_kernel<<<IN_, 256>>>(inp, B.mout, norm_w, norm_b, B.x2);

    // Two FFN heads (share relu(x2)^T split)
    transpose_split<true><<<dim3(SEQ_/32, IN_/32), dim3(32,8)>>>(B.x2, B.xTh, B.xTl, IN_, SEQ_);
    wait_ev(evF);
    launch_ffn(B.x2, Wa1h, Wa1l, Wb1h, Wb1l, out, B);
    launch_ffn(B.x2, Wa2h, Wa2l, Wb2h, Wb2l, out + (long long)IN_ * SEQ_, B);
}

// round 14
// speedup vs baseline: 4.0345x; 1.0823x over previous
#include <cuda_runtime.h>
#include <cuda_bf16.h>
#include <cstdint>

// Problem dims
#define H_   8
#define IN_  512
#define SEQ_ 1024
#define MID_ 2048

// ---------------- HMMA GEMM tile config ----------------
constexpr int BM = 128, BN = 128, BK = 32;     // BK in bf16 k-elements per stage
constexpr int RSB = 80;                        // smem row stride bytes (64 data + 16 pad)
constexpr int OPB = 128 * RSB;                 // bytes per operand-half tile (10240)
constexpr int OFF_AHI = 0, OFF_ALO = OPB, OFF_BHI = 2 * OPB, OFF_BLO = 3 * OPB;
constexpr int STAGE = 4 * OPB;                 // 40960
constexpr int GSMEM = 2 * STAGE;               // 81920 bytes dynamic smem

// ---------------- scratch (device globals; no allocation allowed) ----------------
__device__ float g_mout[IN_ * SEQ_];
__device__ float g_x1  [IN_ * SEQ_];
__device__ float g_x2  [IN_ * SEQ_];
// activation split buffers
__device__ __nv_bfloat16 g_xT_h  [SEQ_ * IN_],           g_xT_l  [SEQ_ * IN_];
__device__ __nv_bfloat16 g_qkvS_h[3 * IN_ * SEQ_],       g_qkvS_l[3 * IN_ * SEQ_];
__device__ __nv_bfloat16 g_hbS_h [H_ * 3 * IN_ * MID_],  g_hbS_l [H_ * 3 * IN_ * MID_];
__device__ __nv_bfloat16 g_qkT_h [2 * H_ * SEQ_ * IN_],  g_qkT_l [2 * H_ * SEQ_ * IN_];
__device__ __nv_bfloat16 g_vS_h  [H_ * IN_ * SEQ_],      g_vS_l  [H_ * IN_ * SEQ_];
__device__ __nv_bfloat16 g_bTS_h [H_ * SEQ_ * SEQ_],     g_bTS_l [H_ * SEQ_ * SEQ_];
__device__ __nv_bfloat16 g_aT_h  [SEQ_ * H_ * IN_],      g_aT_l  [SEQ_ * H_ * IN_];
__device__ __nv_bfloat16 g_zT_h  [SEQ_ * MID_],          g_zT_l  [SEQ_ * MID_];
__device__ __nv_bfloat16 g_zT2_h [SEQ_ * MID_],          g_zT2_l [SEQ_ * MID_];
// per-block weight splits
__device__ __nv_bfloat16 g_wq1_h [3 * IN_ * IN_],        g_wq1_l [3 * IN_ * IN_];
__device__ __nv_bfloat16 g_wq2_h [3 * IN_ * IN_],        g_wq2_l [3 * IN_ * IN_];
__device__ __nv_bfloat16 g_W1a_h [H_ * 3 * MID_ * SEQ_], g_W1a_l [H_ * 3 * MID_ * SEQ_];
__device__ __nv_bfloat16 g_W1b_h [H_ * 3 * MID_ * SEQ_], g_W1b_l [H_ * 3 * MID_ * SEQ_];
__device__ __nv_bfloat16 g_W2a_h [H_ * 3 * SEQ_ * MID_], g_W2a_l [H_ * 3 * SEQ_ * MID_];
__device__ __nv_bfloat16 g_W2b_h [H_ * 3 * SEQ_ * MID_], g_W2b_l [H_ * 3 * SEQ_ * MID_];
__device__ __nv_bfloat16 g_c1a_h [MID_ * H_ * IN_],      g_c1a_l [MID_ * H_ * IN_];
__device__ __nv_bfloat16 g_c1b_h [MID_ * H_ * IN_],      g_c1b_l [MID_ * H_ * IN_];
__device__ __nv_bfloat16 g_c2a_h [IN_ * MID_],           g_c2a_l [IN_ * MID_];
__device__ __nv_bfloat16 g_c2b_h [IN_ * MID_],           g_c2b_l [IN_ * MID_];
__device__ __nv_bfloat16 g_Wa1_h [MID_ * IN_],           g_Wa1_l [MID_ * IN_];
__device__ __nv_bfloat16 g_Wb1_h [IN_ * MID_],           g_Wb1_l [IN_ * MID_];
__device__ __nv_bfloat16 g_Wa2_h [MID_ * IN_],           g_Wa2_l [MID_ * IN_];
__device__ __nv_bfloat16 g_Wb2_h [IN_ * MID_],           g_Wb2_l [IN_ * MID_];

// ---------------- PTX helpers ----------------
__device__ __forceinline__ uint32_t smem_u32(const void* p) {
    uint32_t a;
    asm("{ .reg .u64 t; cvta.to.shared.u64 t, %1; cvt.u32.u64 %0, t; }" : "=r"(a) : "l"(p));
    return a;
}
__device__ __forceinline__ void cpa16(uint32_t d, const void* s) {
    asm volatile("cp.async.cg.shared.global [%0], [%1], 16;" :: "r"(d), "l"(s));
}
__device__ __forceinline__ void cp_commit() {
    asm volatile("cp.async.commit_group;" ::: "memory");
}
template<int N> __device__ __forceinline__ void cp_wait() {
    asm volatile("cp.async.wait_group %0;" :: "n"(N) : "memory");
}
__device__ __forceinline__ void ldsm4(uint32_t& r0, uint32_t& r1, uint32_t& r2, uint32_t& r3, uint32_t a) {
    asm volatile("ldmatrix.sync.aligned.m8n8.x4.shared.b16 {%0,%1,%2,%3}, [%4];"
                 : "=r"(r0), "=r"(r1), "=r"(r2), "=r"(r3) : "r"(a));
}
__device__ __forceinline__ void mma_bf16(float c[4], const uint32_t a[4], const uint32_t b[2]) {
    asm volatile(
        "mma.sync.aligned.m16n8k16.row.col.f32.bf16.bf16.f32 "
        "{%0,%1,%2,%3}, {%4,%5,%6,%7}, {%8,%9}, {%0,%1,%2,%3};\n"
        : "+f"(c[0]), "+f"(c[1]), "+f"(c[2]), "+f"(c[3])
        : "r"(a[0]), "r"(a[1]), "r"(a[2]), "r"(a[3]), "r"(b[0]), "r"(b[1]));
}
__device__ __forceinline__ uint32_t pack2(__nv_bfloat162 h) {
    return *reinterpret_cast<uint32_t*>(&h);
}

// ---------------- GEMM: C = act( A * B^T [+Res] ), operands pre-split bf16 hi/lo ----------------
// Single __syncthreads per k-tile: pattern  wait -> sync -> stage(t+1) -> compute(t).
// The sync guarantees (a) tile t's cp.async data visible to all, (b) every thread
// finished compute(t-1), the last reader of buffer (t+1)&1, so staging it is safe.
template<bool RO, bool RES, int OM>
__global__ void __launch_bounds__(256, 2)
gemm_hmma(const __nv_bfloat16* __restrict__ Ah, const __nv_bfloat16* __restrict__ Al,
          const __nv_bfloat16* __restrict__ Bh, const __nv_bfloat16* __restrict__ Bl,
          float* __restrict__ Cf, __nv_bfloat16* __restrict__ Coh, __nv_bfloat16* __restrict__ Col,
          const float* __restrict__ Res,
          int M, int N, int K, int ldt,
          long long sA1, long long sA2, long long sB1, long long sB2,
          long long sC1, long long sC2, int zdiv)
{
    extern __shared__ char smem[];
    const int tid = threadIdx.x, lane = tid & 31, warp = tid >> 5;

    const int zz = blockIdx.z, zh = zz / zdiv, zc = zz - zh * zdiv;
    const long long offA = zh * sA1 + (long long)zc * sA2;
    const long long offB = zh * sB1 + (long long)zc * sB2;
    const long long cOff = zh * sC1 + (long long)zc * sC2;

    const int bm = blockIdx.y * BM, bn = blockIdx.x * BN;
    const uint32_t sb = smem_u32(smem);

    const int srow = tid >> 2, skq = tid & 3;
    const __nv_bfloat16* pAh = Ah + offA + (long long)(bm + srow) * K + skq * 8;
    const __nv_bfloat16* pAl = Al + offA + (long long)(bm + srow) * K + skq * 8;
    const __nv_bfloat16* pBh = Bh + offB + (long long)(bn + srow) * K + skq * 8;
    const __nv_bfloat16* pBl = Bl + offB + (long long)(bn + srow) * K + skq * 8;
    const long long rstep = 64LL * K;
    const uint32_t sdst = srow * RSB + skq * 16;

    auto stage_load = [&](int t) {
        const int k0 = t * BK;
        const uint32_t d = sb + (t & 1) * STAGE + sdst;
        cpa16(d + OFF_AHI,            pAh + k0);
        cpa16(d + OFF_AHI + 64 * RSB, pAh + k0 + rstep);
        cpa16(d + OFF_ALO,            pAl + k0);
        cpa16(d + OFF_ALO + 64 * RSB, pAl + k0 + rstep);
        cpa16(d + OFF_BHI,            pBh + k0);
        cpa16(d + OFF_BHI + 64 * RSB, pBh + k0 + rstep);
        cpa16(d + OFF_BLO,            pBl + k0);
        cpa16(d + OFF_BLO + 64 * RSB, pBl + k0 + rstep);
        cp_commit();
    };

    float acc[4][4][4];
#pragma unroll
    for (int i = 0; i < 4; ++i)
#pragma unroll
        for (int j = 0; j < 4; ++j)
#pragma unroll
            for (int r = 0; r < 4; ++r) acc[i][j][r] = 0.f;

    const int wm = (warp & 1) * 64, wn = (warp >> 1) * 32;
    const int aRow   = wm + (lane & 7) + ((lane >> 3) & 1) * 8;
    const int aChunk = (lane >> 4) * 16;
    const int bRow   = wn + (lane & 7) + (lane >> 4) * 8;
    const int bChunk = ((lane >> 3) & 1) * 16;

    stage_load(0);
    const int nk = K / BK;

    for (int t = 0; t < nk; ++t) {
        cp_wait<0>();
        __syncthreads();                       // single barrier per k-tile
        if (t + 1 < nk) stage_load(t + 1);     // safe: see header comment

        const uint32_t ss = sb + (t & 1) * STAGE;
#pragma unroll
        for (int kk = 0; kk < 2; ++kk) {
            const uint32_t kb = kk * 32;
            uint32_t ah[4][4], bh2[4][2], bl2[4][2];
#pragma unroll
            for (int i = 0; i < 4; ++i)
                ldsm4(ah[i][0], ah[i][1], ah[i][2], ah[i][3],
                      ss + OFF_AHI + (aRow + i * 16) * RSB + kb + aChunk);
#pragma unroll
            for (int jj = 0; jj < 2; ++jj) {
                uint32_t r0, r1, r2, r3;
                ldsm4(r0, r1, r2, r3, ss + OFF_BHI + (bRow + jj * 16) * RSB + kb + bChunk);
                bh2[2 * jj][0] = r0; bh2[2 * jj][1] = r1;
                bh2[2 * jj + 1][0] = r2; bh2[2 * jj + 1][1] = r3;
            }
#pragma unroll
            for (int i = 0; i < 4; ++i)
#pragma unroll
                for (int j = 0; j < 4; ++j) mma_bf16(acc[i][j], ah[i], bh2[j]);
#pragma unroll
            for (int jj = 0; jj < 2; ++jj) {
                uint32_t r0, r1, r2, r3;
                ldsm4(r0, r1, r2, r3, ss + OFF_BLO + (bRow + jj * 16) * RSB + kb + bChunk);
                bl2[2 * jj][0] = r0; bl2[2 * jj][1] = r1;
                bl2[2 * jj + 1][0] = r2; bl2[2 * jj + 1][1] = r3;
            }
#pragma unroll
            for (int i = 0; i < 4; ++i)
#pragma unroll
                for (int j = 0; j < 4; ++j) mma_bf16(acc[i][j], ah[i], bl2[j]);
#pragma unroll
            for (int i = 0; i < 4; ++i)
                ldsm4(ah[i][0], ah[i][1], ah[i][2], ah[i][3],
                      ss + OFF_ALO + (aRow + i * 16) * RSB + kb + aChunk);
#pragma unroll
            for (int i = 0; i < 4; ++i)
#pragma unroll
                for (int j = 0; j < 4; ++j) mma_bf16(acc[i][j], ah[i], bh2[j]);
        }
    }

    const int ar = lane >> 2, ac = lane & 3;

    if (OM == 2) {
        __syncthreads();   // all warps done reading stage smem before reuse as transpose buffer
        float* tb = reinterpret_cast<float*>(smem);
        const int TLD = 132;
#pragma unroll
        for (int i = 0; i < 4; ++i) {
            int m0 = wm + i * 16 + ar;
#pragma unroll
            for (int j = 0; j < 4; ++j) {
                int n0 = wn + j * 8 + ac * 2;
                float v0 = acc[i][j][0], v1 = acc[i][j][1];
                float v2 = acc[i][j][2], v3 = acc[i][j][3];
                if (RO) {
                    v0 = fmaxf(v0, 0.f); v1 = fmaxf(v1, 0.f);
                    v2 = fmaxf(v2, 0.f); v3 = fmaxf(v3, 0.f);
                }
                tb[n0 * TLD + m0]           = v0;
                tb[(n0 + 1) * TLD + m0]     = v1;
                tb[n0 * TLD + m0 + 8]       = v2;
                tb[(n0 + 1) * TLD + m0 + 8] = v3;
            }
        }
        __syncthreads();
        const int n = tid >> 1, mh = (tid & 1) * 64;
        const long long ro = cOff + (long long)(bn + n) * ldt + bm + mh;
#pragma unroll
        for (int mm = 0; mm < 64; mm += 8) {
            float4 a = *reinterpret_cast<float4*>(&tb[n * TLD + mh + mm]);
            float4 b = *reinterpret_cast<float4*>(&tb[n * TLD + mh + mm + 4]);
            __nv_bfloat162 h0 = __floats2bfloat162_rn(a.x, a.y), h1 = __floats2bfloat162_rn(a.z, a.w);
            __nv_bfloat162 h2 = __floats2bfloat162_rn(b.x, b.y), h3 = __floats2bfloat162_rn(b.z, b.w);
            __nv_bfloat162 l0 = __floats2bfloat162_rn(a.x - __bfloat162float(h0.x), a.y - __bfloat162float(h0.y));
            __nv_bfloat162 l1 = __floats2bfloat162_rn(a.z - __bfloat162float(h1.x), a.w - __bfloat162float(h1.y));
            __nv_bfloat162 l2 = __floats2bfloat162_rn(b.x - __bfloat162float(h2.x), b.y - __bfloat162float(h2.y));
            __nv_bfloat162 l3 = __floats2bfloat162_rn(b.z - __bfloat162float(h3.x), b.w - __bfloat162float(h3.y));
            *reinterpret_cast<uint4*>(Coh + ro + mm) = make_uint4(pack2(h0), pack2(h1), pack2(h2), pack2(h3));
            *reinterpret_cast<uint4*>(Col + ro + mm) = make_uint4(pack2(l0), pack2(l1), pack2(l2), pack2(l3));
        }
        return;
    }

#pragma unroll
    for (int i = 0; i < 4; ++i) {
        int m0 = bm + wm + i * 16 + ar;
#pragma unroll
        for (int j = 0; j < 4; ++j) {
            int n0 = bn + wn + j * 8 + ac * 2;
            long long o0 = cOff + (long long)m0 * N + n0;
            long long o1 = o0 + 8LL * N;
            float v0 = acc[i][j][0], v1 = acc[i][j][1];
            float v2 = acc[i][j][2], v3 = acc[i][j][3];
            if (RES) {
                v0 += Res[o0]; v1 += Res[o0 + 1];
                v2 += Res[o1]; v3 += Res[o1 + 1];
            }
            if (RO) {
                v0 = fmaxf(v0, 0.f); v1 = fmaxf(v1, 0.f);
                v2 = fmaxf(v2, 0.f); v3 = fmaxf(v3, 0.f);
            }
            if (OM == 0) {
                *reinterpret_cast<float2*>(Cf + o0) = make_float2(v0, v1);
                *reinterpret_cast<float2*>(Cf + o1) = make_float2(v2, v3);
            } else {
                __nv_bfloat162 h0 = __floats2bfloat162_rn(v0, v1);
                __nv_bfloat162 l0 = __floats2bfloat162_rn(v0 - __bfloat162float(h0.x),
                                                          v1 - __bfloat162float(h0.y));
                __nv_bfloat162 h1 = __floats2bfloat162_rn(v2, v3);
                __nv_bfloat162 l1 = __floats2bfloat162_rn(v2 - __bfloat162float(h1.x),
                                                          v3 - __bfloat162float(h1.y));
                reinterpret_cast<__nv_bfloat162*>(Coh)[o0 >> 1] = h0;
                reinterpret_cast<__nv_bfloat162*>(Col)[o0 >> 1] = l0;
                reinterpret_cast<__nv_bfloat162*>(Coh)[o1 >> 1] = h1;
                reinterpret_cast<__nv_bfloat162*>(Col)[o1 >> 1] = l1;
            }
        }
    }
}

// ---------------- split (same layout): fp32 -> bf16 hi/lo ----------------
__global__ void split_rm(const float* __restrict__ in,
                         __nv_bfloat16* __restrict__ oh, __nv_bfloat16* __restrict__ ol,
                         long long n)
{
    long long i = ((long long)blockIdx.x * blockDim.x + threadIdx.x) * 4;
    if (i >= n) return;
    float4 v = *reinterpret_cast<const float4*>(in + i);
    __nv_bfloat162 h0 = __floats2bfloat162_rn(v.x, v.y);
    __nv_bfloat162 h1 = __floats2bfloat162_rn(v.z, v.w);
    __nv_bfloat162 l0 = __floats2bfloat162_rn(v.x - __bfloat162float(h0.x), v.y - __bfloat162float(h0.y));
    __nv_bfloat162 l1 = __floats2bfloat162_rn(v.z - __bfloat162float(h1.x), v.w - __bfloat162float(h1.y));
    *reinterpret_cast<uint2*>(oh + i) = make_uint2(pack2(h0), pack2(h1));
    *reinterpret_cast<uint2*>(ol + i) = make_uint2(pack2(l0), pack2(l1));
}

// ---------------- transpose + split: fp32 (R,C) -> bf16 hi/lo (C,R) ----------------
template<bool RELU>
__global__ void transpose_split(const float* __restrict__ in,
                                __nv_bfloat16* __restrict__ oh, __nv_bfloat16* __restrict__ ol,
                                int R, int C)
{
    __shared__ float tile[32][33];
    const int tx = threadIdx.x, ty = threadIdx.y;
    const int r0 = blockIdx.y * 32, c0 = blockIdx.x * 32;
#pragma unroll
    for (int i = 0; i < 4; ++i)
        tile[ty + 8 * i][tx] = in[(long long)(r0 + ty + 8 * i) * C + c0 + tx];
    __syncthreads();
#pragma unroll
    for (int i = 0; i < 4; ++i) {
        int c = c0 + ty + 8 * i, r = r0 + tx;
        float v = tile[tx][ty + 8 * i];
        if (RELU) v = fmaxf(v, 0.f);
        __nv_bfloat16 h = __float2bfloat16(v);
        __nv_bfloat16 l = __float2bfloat16(v - __bfloat162float(h));
        oh[(long long)c * R + r] = h;
        ol[(long long)c * R + r] = l;
    }
}

// ---------------- fused residual add + layernorm over last axis (1024) ----------------
__global__ void add_ln_kernel(const float* __restrict__ a, const float* __restrict__ b,
                              const float* __restrict__ w, const float* __restrict__ bias,
                              float* __restrict__ out)
{
    const int row = blockIdx.x;
    const int tid = threadIdx.x;
    const long long base = (long long)row * SEQ_;
    float v[4];
    float s = 0.f, ss = 0.f;
#pragma unroll
    for (int i = 0; i < 4; ++i) {
        int col = tid + i * 256;
        float t = a[base + col] + b[base + col];
        v[i] = t; s += t; ss += t * t;
    }
#pragma unroll
    for (int o = 16; o > 0; o >>= 1) {
        s  += __shfl_xor_sync(0xffffffffu, s,  o);
        ss += __shfl_xor_sync(0xffffffffu, ss, o);
    }
    __shared__ float rs[8], rss[8];
    if ((tid & 31) == 0) { rs[tid >> 5] = s; rss[tid >> 5] = ss; }
    __syncthreads();
    s = 0.f; ss = 0.f;
#pragma unroll
    for (int i = 0; i < 8; ++i) { s += rs[i]; ss += rss[i]; }
    const float mu  = s  * (1.0f / SEQ_);
    const float var = ss * (1.0f / SEQ_) - mu * mu;
    const float inv = rsqrtf(var + 1e-6f);
#pragma unroll
    for (int i = 0; i < 4; ++i) {
        int col = tid + i * 256;
        out[base + col] = (v[i] - mu) * inv * w[col] + bias[col];
    }
}

// ---------------- host orchestration ----------------
struct WSet {
    __nv_bfloat16 *wqh, *wql, *W1h, *W1l, *W2h, *W2l, *c1h, *c1l, *c2h, *c2l;
};
struct Bufs {
    float *mout, *x1, *x2;
    __nv_bfloat16 *xTh, *xTl, *qh, *ql, *hbh, *hbl, *qkTh, *qkTl,
                  *vh, *vl, *bTh, *bTl, *aTh, *aTl, *zTh, *zTl, *zT2h, *zT2l;
};

static inline unsigned nb4(long long n) { return (unsigned)((n / 4 + 255) / 256); }
static inline void wait_ev(cudaEvent_t ev) { cudaStreamWaitEvent((cudaStream_t)0, ev, 0); }

static cudaStream_t s2;
static cudaEvent_t evS, evA, evB, evC, evD, evE, evF, evG, evH, evI, evJ;

// One MHA block. Weight-ready events already satisfied by caller. The v-projection
// GEMM runs on s2 concurrently with the bT GEMM (independent DAG branches).
static void launch_mha(const WSet& W, const Bufs& B)
{
    const long long IS = (long long)IN_ * SEQ_;
    const long long IM = (long long)IN_ * MID_;
    const long long SM = (long long)SEQ_ * MID_;
    const long long SI = (long long)SEQ_ * IN_;

    gemm_hmma<true,false,1><<<dim3(SEQ_/BN, IN_/BM, 3), 256, GSMEM>>>(
        W.wqh, W.wql, B.xTh, B.xTl, nullptr, B.qh, B.ql, nullptr,
        IN_, SEQ_, IN_, 0, (long long)IN_*IN_, 0, 0, 0, IS, 0, 1);

    gemm_hmma<true,false,1><<<dim3(MID_/BN, IN_/BM, H_*3), 256, GSMEM>>>(
        B.qh, B.ql, W.W1h, W.W1l, nullptr, B.hbh, B.hbl, nullptr,
        IN_, MID_, SEQ_, 0, 0, IS,
        3LL*MID_*SEQ_, (long long)MID_*SEQ_, 3*IM, IM, 3);
    cudaEventRecord(evG, 0);

    // v projection on s2 (independent of qk path)
    cudaStreamWaitEvent(s2, evG, 0);
    gemm_hmma<false,false,1><<<dim3(SEQ_/BN, IN_/BM, H_), 256, GSMEM, s2>>>(
        B.hbh + 2*IM, B.hbl + 2*IM, W.W2h + 2*SM, W.W2l + 2*SM, nullptr, B.vh, B.vl, nullptr,
        IN_, SEQ_, MID_, 0, 3*IM, 0, 3*SM, 0, IS, 0, 1);
    cudaEventRecord(evH, s2);

    // qk path on main
    gemm_hmma<false,false,2><<<dim3(SEQ_/BN, IN_/BM, H_*2), 256, GSMEM>>>(
        B.hbh, B.hbl, W.W2h, W.W2l, nullptr, B.qkTh, B.qkTl, nullptr,
        IN_, SEQ_, MID_, IN_, 3*IM, IM, 3*SM, SM, SI, (long long)H_*SI, 2);

    gemm_hmma<false,false,1><<<dim3(SEQ_/BN, SEQ_/BM, H_), 256, GSMEM>>>(
        B.qkTh, B.qkTl, B.qkTh + (long long)H_*SI, B.qkTl + (long long)H_*SI,
        nullptr, B.bTh, B.bTl, nullptr,
        SEQ_, SEQ_, IN_, 0, SI, 0, SI, 0, (long long)SEQ_*SEQ_, 0, 1);

    wait_ev(evH);
    gemm_hmma<true,false,2><<<dim3(SEQ_/BN, IN_/BM, H_), 256, GSMEM>>>(
        B.vh, B.vl, B.bTh, B.bTl, nullptr, B.aTh, B.aTl, nullptr,
        IN_, SEQ_, SEQ_, H_*IN_, IS, 0, (long long)SEQ_*SEQ_, 0, IN_, 0, 1);

    gemm_hmma<true,false,2><<<dim3(SEQ_/BN, MID_/BM, 1), 256, GSMEM>>>(
        W.c1h, W.c1l, B.aTh, B.aTl, nullptr, B.zTh, B.zTl, nullptr,
        MID_, SEQ_, H_*IN_, MID_, 0,0, 0,0, 0,0, 1);

    gemm_hmma<false,false,0><<<dim3(SEQ_/BN, IN_/BM, 1), 256, GSMEM>>>(
        W.c2h, W.c2l, B.zTh, B.zTl, B.mout,
        (__nv_bfloat16*)nullptr, (__nv_bfloat16*)nullptr, nullptr,
        IN_, SEQ_, MID_, 0, 0,0, 0,0, 0,0, 1);
}

static void launch_ffn(const float* x2,
                       const __nv_bfloat16* Wah, const __nv_bfloat16* Wal,
                       const __nv_bfloat16* Wbh, const __nv_bfloat16* Wbl,
                       __nv_bfloat16* zh, __nv_bfloat16* zl,
                       const __nv_bfloat16* xTh, const __nv_bfloat16* xTl,
                       float* out, cudaStream_t st)
{
    gemm_hmma<true,false,2><<<dim3(SEQ_/BN, MID_/BM, 1), 256, GSMEM, st>>>(
        Wah, Wal, xTh, xTl, nullptr, zh, zl, nullptr,
        MID_, SEQ_, IN_, MID_, 0,0, 0,0, 0,0, 1);
    gemm_hmma<false,true,0><<<dim3(SEQ_/BN, IN_/BM, 1), 256, GSMEM, st>>>(
        Wbh, Wbl, zh, zl, out,
        (__nv_bfloat16*)nullptr, (__nv_bfloat16*)nullptr, x2,
        IN_, SEQ_, MID_, 0, 0,0, 0,0, 0,0, 1);
}

extern "C" void kernel_launch(void* const* d_in, const int* in_sizes, int n_in,
                              void* d_out, int out_size)
{
    (void)in_sizes; (void)n_in; (void)out_size;

    const float* inp     = (const float*)d_in[0];
    const float* w_qkv_1 = (const float*)d_in[1];
    const float* w_qkv_2 = (const float*)d_in[2];
    const float* mh1_W1  = (const float*)d_in[3];
    const float* mh1_W2  = (const float*)d_in[4];
    const float* mh2_W1  = (const float*)d_in[5];
    const float* mh2_W2  = (const float*)d_in[6];
    const float* c1_W1   = (const float*)d_in[7];
    const float* c1_W2   = (const float*)d_in[8];
    const float* c2_W1   = (const float*)d_in[9];
    const float* c2_W2   = (const float*)d_in[10];
    const float* l1_W1   = (const float*)d_in[11];
    const float* l1_W2   = (const float*)d_in[12];
    const float* l2_W1   = (const float*)d_in[13];
    const float* l2_W2   = (const float*)d_in[14];
    const float* norm_w  = (const float*)d_in[15];
    const float* norm_b  = (const float*)d_in[16];
    float* out = (float*)d_out;

    static bool inited = false;
    if (!inited) {
        cudaStreamCreateWithFlags(&s2, cudaStreamNonBlocking);
        cudaEvent_t* evs[] = {&evS,&evA,&evB,&evC,&evD,&evE,&evF,&evG,&evH,&evI,&evJ};
        for (auto e : evs) cudaEventCreateWithFlags(e, cudaEventDisableTiming);
        cudaFuncSetAttribute(gemm_hmma<true,false,1>,  cudaFuncAttributeMaxDynamicSharedMemorySize, GSMEM);
        cudaFuncSetAttribute(gemm_hmma<false,false,1>, cudaFuncAttributeMaxDynamicSharedMemorySize, GSMEM);
        cudaFuncSetAttribute(gemm_hmma<false,false,2>, cudaFuncAttributeMaxDynamicSharedMemorySize, GSMEM);
        cudaFuncSetAttribute(gemm_hmma<true,false,2>,  cudaFuncAttributeMaxDynamicSharedMemorySize, GSMEM);
        cudaFuncSetAttribute(gemm_hmma<false,false,0>, cudaFuncAttributeMaxDynamicSharedMemorySize, GSMEM);
        cudaFuncSetAttribute(gemm_hmma<false,true,0>,  cudaFuncAttributeMaxDynamicSharedMemorySize, GSMEM);
        inited = true;
    }

    Bufs B;
    cudaGetSymbolAddress((void**)&B.mout, g_mout);
    cudaGetSymbolAddress((void**)&B.x1,   g_x1);
    cudaGetSymbolAddress((void**)&B.x2,   g_x2);
    cudaGetSymbolAddress((void**)&B.xTh,  g_xT_h);   cudaGetSymbolAddress((void**)&B.xTl,  g_xT_l);
    cudaGetSymbolAddress((void**)&B.qh,   g_qkvS_h); cudaGetSymbolAddress((void**)&B.ql,   g_qkvS_l);
    cudaGetSymbolAddress((void**)&B.hbh,  g_hbS_h);  cudaGetSymbolAddress((void**)&B.hbl,  g_hbS_l);
    cudaGetSymbolAddress((void**)&B.qkTh, g_qkT_h);  cudaGetSymbolAddress((void**)&B.qkTl, g_qkT_l);
    cudaGetSymbolAddress((void**)&B.vh,   g_vS_h);   cudaGetSymbolAddress((void**)&B.vl,   g_vS_l);
    cudaGetSymbolAddress((void**)&B.bTh,  g_bTS_h);  cudaGetSymbolAddress((void**)&B.bTl,  g_bTS_l);
    cudaGetSymbolAddress((void**)&B.aTh,  g_aT_h);   cudaGetSymbolAddress((void**)&B.aTl,  g_aT_l);
    cudaGetSymbolAddress((void**)&B.zTh,  g_zT_h);   cudaGetSymbolAddress((void**)&B.zTl,  g_zT_l);
    cudaGetSymbolAddress((void**)&B.zT2h, g_zT2_h);  cudaGetSymbolAddress((void**)&B.zT2l, g_zT2_l);

    WSet W1s, W2s;
    cudaGetSymbolAddress((void**)&W1s.wqh, g_wq1_h); cudaGetSymbolAddress((void**)&W1s.wql, g_wq1_l);
    cudaGetSymbolAddress((void**)&W1s.W1h, g_W1a_h); cudaGetSymbolAddress((void**)&W1s.W1l, g_W1a_l);
    cudaGetSymbolAddress((void**)&W1s.W2h, g_W2a_h); cudaGetSymbolAddress((void**)&W1s.W2l, g_W2a_l);
    cudaGetSymbolAddress((void**)&W1s.c1h, g_c1a_h); cudaGetSymbolAddress((void**)&W1s.c1l, g_c1a_l);
    cudaGetSymbolAddress((void**)&W1s.c2h, g_c2a_h); cudaGetSymbolAddress((void**)&W1s.c2l, g_c2a_l);
    cudaGetSymbolAddress((void**)&W2s.wqh, g_wq2_h); cudaGetSymbolAddress((void**)&W2s.wql, g_wq2_l);
    cudaGetSymbolAddress((void**)&W2s.W1h, g_W1b_h); cudaGetSymbolAddress((void**)&W2s.W1l, g_W1b_l);
    cudaGetSymbolAddress((void**)&W2s.W2h, g_W2b_h); cudaGetSymbolAddress((void**)&W2s.W2l, g_W2b_l);
    cudaGetSymbolAddress((void**)&W2s.c1h, g_c1b_h); cudaGetSymbolAddress((void**)&W2s.c1l, g_c1b_l);
    cudaGetSymbolAddress((void**)&W2s.c2h, g_c2b_h); cudaGetSymbolAddress((void**)&W2s.c2l, g_c2b_l);
    __nv_bfloat16 *Wa1h, *Wa1l, *Wb1h, *Wb1l, *Wa2h, *Wa2l, *Wb2h, *Wb2l;
    cudaGetSymbolAddress((void**)&Wa1h, g_Wa1_h); cudaGetSymbolAddress((void**)&Wa1l, g_Wa1_l);
    cudaGetSymbolAddress((void**)&Wb1h, g_Wb1_h); cudaGetSymbolAddress((void**)&Wb1l, g_Wb1_l);
    cudaGetSymbolAddress((void**)&Wa2h, g_Wa2_h); cudaGetSymbolAddress((void**)&Wa2l, g_Wa2_l);
    cudaGetSymbolAddress((void**)&Wb2h, g_Wb2_h); cudaGetSymbolAddress((void**)&Wb2l, g_Wb2_l);

    const long long nWQ = 3LL*IN_*IN_, nW1 = 24LL*MID_*SEQ_, nW2 = 24LL*SEQ_*MID_;
    const long long nC1 = (long long)MID_*H_*IN_, nC2 = (long long)IN_*MID_;
    const long long nWa = (long long)MID_*IN_, nWb = (long long)IN_*MID_;

    // ---- fork side stream: all weight splits overlap the GEMM chain ----
    cudaEventRecord(evS, 0);
    cudaStreamWaitEvent(s2, evS, 0);
    split_rm<<<nb4(nWQ), 256, 0, s2>>>(w_qkv_1, W1s.wqh, W1s.wql, nWQ);
    cudaEventRecord(evA, s2);
    split_rm<<<nb4(nW1), 256, 0, s2>>>(mh1_W1, W1s.W1h, W1s.W1l, nW1);
    cudaEventRecord(evB, s2);
    split_rm<<<nb4(nW2), 256, 0, s2>>>(mh1_W2, W1s.W2h, W1s.W2l, nW2);
    cudaEventRecord(evC, s2);
    split_rm<<<nb4(nC1), 256, 0, s2>>>(c1_W1, W1s.c1h, W1s.c1l, nC1);
    split_rm<<<nb4(nC2), 256, 0, s2>>>(c1_W2, W1s.c2h, W1s.c2l, nC2);
    cudaEventRecord(evD, s2);
    split_rm<<<nb4(nWQ), 256, 0, s2>>>(w_qkv_2, W2s.wqh, W2s.wql, nWQ);
    split_rm<<<nb4(nW1), 256, 0, s2>>>(mh2_W1, W2s.W1h, W2s.W1l, nW1);
    split_rm<<<nb4(nW2), 256, 0, s2>>>(mh2_W2, W2s.W2h, W2s.W2l, nW2);
    split_rm<<<nb4(nC1), 256, 0, s2>>>(c2_W1, W2s.c1h, W2s.c1l, nC1);
    split_rm<<<nb4(nC2), 256, 0, s2>>>(c2_W2, W2s.c2h, W2s.c2l, nC2);
    cudaEventRecord(evE, s2);
    split_rm<<<nb4(nWa), 256, 0, s2>>>(l1_W1, Wa1h, Wa1l, nWa);
    split_rm<<<nb4(nWb), 256, 0, s2>>>(l1_W2, Wb1h, Wb1l, nWb);
    split_rm<<<nb4(nWa), 256, 0, s2>>>(l2_W1, Wa2h, Wa2l, nWa);
    split_rm<<<nb4(nWb), 256, 0, s2>>>(l2_W2, Wb2h, Wb2l, nWb);
    cudaEventRecord(evF, s2);

    // ---- Block 1: x1 = LN(inp + MHA1(inp)) ---- (fine-grained weight waits)
    transpose_split<false><<<dim3(SEQ_/32, IN_/32), dim3(32,8)>>>(inp, B.xTh, B.xTl, IN_, SEQ_);
    wait_ev(evA);
    {
        const long long IM = (long long)IN_*MID_, SM = (long long)SEQ_*MID_,
                        SI = (long long)SEQ_*IN_, IS = (long long)IN_*SEQ_;
        gemm_hmma<true,false,1><<<dim3(SEQ_/BN, IN_/BM, 3), 256, GSMEM>>>(
            W1s.wqh, W1s.wql, B.xTh, B.xTl, nullptr, B.qh, B.ql, nullptr,
            IN_, SEQ_, IN_, 0, (long long)IN_*IN_, 0, 0, 0, IS, 0, 1);
        wait_ev(evB);
        gemm_hmma<true,false,1><<<dim3(MID_/BN, IN_/BM, H_*3), 256, GSMEM>>>(
            B.qh, B.ql, W1s.W1h, W1s.W1l, nullptr, B.hbh, B.hbl, nullptr,
            IN_, MID_, SEQ_, 0, 0, IS,
            3LL*MID_*SEQ_, (long long)MID_*SEQ_, 3*IM, IM, 3);
        wait_ev(evC);
        cudaEventRecord(evG, 0);
        // v projection on s2
        cudaStreamWaitEvent(s2, evG, 0);
        gemm_hmma<false,false,1><<<dim3(SEQ_/BN, IN_/BM, H_), 256, GSMEM, s2>>>(
            B.hbh + 2*IM, B.hbl + 2*IM, W1s.W2h + 2*SM, W1s.W2l + 2*SM, nullptr, B.vh, B.vl, nullptr,
            IN_, SEQ_, MID_, 0, 3*IM, 0, 3*SM, 0, IS, 0, 1);
        cudaEventRecord(evH, s2);
        // qk path
        gemm_hmma<false,false,2><<<dim3(SEQ_/BN, IN_/BM, H_*2), 256, GSMEM>>>(
            B.hbh, B.hbl, W1s.W2h, W1s.W2l, nullptr, B.qkTh, B.qkTl, nullptr,
            IN_, SEQ_, MID_, IN_, 3*IM, IM, 3*SM, SM, SI, (long long)H_*SI, 2);
        gemm_hmma<false,false,1><<<dim3(SEQ_/BN, SEQ_/BM, H_), 256, GSMEM>>>(
            B.qkTh, B.qkTl, B.qkTh + (long long)H_*SI, B.qkTl + (long long)H_*SI,
            nullptr, B.bTh, B.bTl, nullptr,
            SEQ_, SEQ_, IN_, 0, SI, 0, SI, 0, (long long)SEQ_*SEQ_, 0, 1);
        wait_ev(evH);
        gemm_hmma<true,false,2><<<dim3(SEQ_/BN, IN_/BM, H_), 256, GSMEM>>>(
            B.vh, B.vl, B.bTh, B.bTl, nullptr, B.aTh, B.aTl, nullptr,
            IN_, SEQ_, SEQ_, H_*IN_, IS, 0, (long long)SEQ_*SEQ_, 0, IN_, 0, 1);
        wait_ev(evD);
        gemm_hmma<true,false,2><<<dim3(SEQ_/BN, MID_/BM, 1), 256, GSMEM>>>(
            W1s.c1h, W1s.c1l, B.aTh, B.aTl, nullptr, B.zTh, B.zTl, nullptr,
            MID_, SEQ_, H_*IN_, MID_, 0,0, 0,0, 0,0, 1);
        gemm_hmma<false,false,0><<<dim3(SEQ_/BN, IN_/BM, 1), 256, GSMEM>>>(
            W1s.c2h, W1s.c2l, B.zTh, B.zTl, B.mout,
            (__nv_bfloat16*)nullptr, (__nv_bfloat16*)nullptr, nullptr,
            IN_, SEQ_, MID_, 0, 0,0, 0,0, 0,0, 1);
    }
    add_ln_kernel<<<IN_, 256>>>(inp, B.mout, norm_w, norm_b, B.x1);

    // ---- Block 2: x2 = LN(inp + MHA2(x1)) ----
    transpose_split<false><<<dim3(SEQ_/32, IN_/32), dim3(32,8)>>>(B.x1, B.xTh, B.xTl, IN_, SEQ_);
    wait_ev(evE);
    launch_mha(W2s, B);
    add_ln_kernel<<<IN_, 256>>>(inp, B.mout, norm_w, norm_b, B.x2);

    // ---- Two FFN heads, concurrently on main and s2 ----
    transpose_split<true><<<dim3(SEQ_/32, IN_/32), dim3(32,8)>>>(B.x2, B.xTh, B.xTl, IN_, SEQ_);
    wait_ev(evF);
    cudaEventRecord(evI, 0);
    cudaStreamWaitEvent(s2, evI, 0);
    launch_ffn(B.x2, Wa2h, Wa2l, Wb2h, Wb2l, B.zT2h, B.zT2l, B.xTh, B.xTl,
               out + (long long)IN_ * SEQ_, s2);
    cudaEventRecord(evJ, s2);
    launch_ffn(B.x2, Wa1h, Wa1l, Wb1h, Wb1l, B.zTh, B.zTl, B.xTh, B.xTl,
               out, (cudaStream_t)0);
    wait_ev(evJ);
}